// round 7
// baseline (speedup 1.0000x reference)
#include <cuda_runtime.h>
#include <cuda_fp16.h>
#include <cstdint>

#define NN 4096
#define NB 32
#define PA 3072      /* u32 per fragment panel: 128 rows/cols x 48 k fp16 pairs */
#define SCALE2 (0.28867513459481287f * 1.4426950408889634f)  /* (1/sqrt12)*log2e */

typedef unsigned int u32;

/* ---------------- global scratch ----------------------------------------- */
__device__ __align__(16) u32   g_qA[8*NB*PA];     /* Q as mma-A frags (pass2) */
__device__ __align__(16) u32   g_qB[8*NB*PA];     /* Q as mma-B frags (pass1) */
__device__ __align__(16) u32   g_kA[8*NB*PA];     /* K as mma-A frags (pass1) */
__device__ __align__(16) u32   g_kB[8*NB*PA];     /* K as mma-B frags (pass2) */
__device__ __align__(16) u32   g_vB[8*NB*PA];     /* v/D as mma-B frags (pass2) */
__device__ __align__(16) float g_v [8*48*NN];     /* fp32 v, rows 36..47 zero */

/* ---------------- helpers ------------------------------------------------ */
__device__ __forceinline__ void mma_h(float* d, uint4 a, uint2 b){
    asm("mma.sync.aligned.m16n8k16.row.col.f32.f16.f16.f32 "
        "{%0,%1,%2,%3},{%4,%5,%6,%7},{%8,%9},{%0,%1,%2,%3};"
        : "+f"(d[0]), "+f"(d[1]), "+f"(d[2]), "+f"(d[3])
        : "r"(a.x), "r"(a.y), "r"(a.z), "r"(a.w), "r"(b.x), "r"(b.y));
}
__device__ __forceinline__ u32 pkh(float lo, float hi){
    __half2 h = __floats2half2_rn(lo, hi);
    return *(u32*)&h;
}
__device__ __forceinline__ float ex2f(float x){
    float r; asm("ex2.approx.f32 %0, %1;" : "=f"(r) : "f"(x)); return r;
}
__device__ __forceinline__ u32 smem_u32(const void* p){
    u32 a;
    asm("{ .reg .u64 t; cvta.to.shared.u64 t, %1; cvt.u32.u64 %0, t; }" : "=r"(a) : "l"(p));
    return a;
}
__device__ __forceinline__ void cpa16(u32 d, const void* s){
    asm volatile("cp.async.ca.shared.global [%0], [%1], 16;" :: "r"(d), "l"(s));
}
#define CP_COMMIT() asm volatile("cp.async.commit_group;")
#define CP_WAIT1()  asm volatile("cp.async.wait_group 1;")
#define CP_WAIT0()  asm volatile("cp.async.wait_group 0;")

/* ================= Kernel A: QKV -> fp16 fragment panels (x4) ============ */
__global__ __launch_bounds__(128)
void qkv_kernel(const float* __restrict__ x,
                const float* __restrict__ wq, const float* __restrict__ bq,
                const float* __restrict__ wk, const float* __restrict__ bk,
                const float* __restrict__ wv, const float* __restrict__ bv)
{
    __shared__ float w_s[3*432];
    __shared__ float b_s[3*36];
    const int t = threadIdx.x;
    const int b = blockIdx.y, nblk = blockIdx.x;
    const int n = nblk*128 + t;

    for (int i = t; i < 432; i += 128){ w_s[i]=wq[i]; w_s[432+i]=wk[i]; w_s[864+i]=wv[i]; }
    if (t < 36){ b_s[t]=bq[t]; b_s[36+t]=bk[t]; b_s[72+t]=bv[t]; }
    __syncthreads();

    float xv[12];
    #pragma unroll
    for (int c = 0; c < 12; ++c) xv[c] = x[(b*12 + c)*NN + n];

    float qv[36], kv[36];
    #pragma unroll 4
    for (int o = 0; o < 36; ++o){
        float q = b_s[o], k = b_s[36+o], v = b_s[72+o];
        #pragma unroll
        for (int c = 0; c < 12; ++c){
            q += w_s[o*12+c]*xv[c];
            k += w_s[432+o*12+c]*xv[c];
            v += w_s[864+o*12+c]*xv[c];
        }
        qv[o] = q*SCALE2;   /* fold softmax scale AND log2e */
        kv[o] = k;
        g_v[((long)(b*48+o))*NN + n] = v;
    }
    #pragma unroll
    for (int o = 36; o < 48; ++o) g_v[((long)(b*48+o))*NN + n] = 0.f;

    const int base = (b*NB + nblk)*PA;
    const int rt = t >> 4, lr = t & 15;     /* A coords: row = t */
    const int ct = t >> 3, gB = t & 7;      /* B coords: col = t */

    #pragma unroll
    for (int p = 0; p < 24; ++p){
        const int kk = p >> 3, cp = p & 7;
        const int c0 = kk*16 + cp*2, c1 = c0 + 1;
        const float q0 = (c0 < 36) ? qv[c0] : 0.f, q1 = (c1 < 36) ? qv[c1] : 0.f;
        const float k0 = (c0 < 36) ? kv[c0] : 0.f, k1 = (c1 < 36) ? kv[c1] : 0.f;
        const u32 qp = pkh(q0, q1), kp = pkh(k0, k1);
        /* A-frags */
        const int regA  = ((cp >> 2) << 1) | (lr >> 3);
        const int laneA = ((lr & 7) << 2) | (cp & 3);
        const int aoff  = base + (rt*3 + kk)*128 + laneA*4 + regA;
        g_qA[aoff] = qp;
        g_kA[aoff] = kp;
        /* B-frags */
        const int regB  = cp >> 2;
        const int laneB = (gB << 2) | (cp & 3);
        const int boff  = base + (ct*3 + kk)*64 + laneB*2 + regB;
        g_qB[boff] = qp;
        g_kB[boff] = kp;
    }
}

/* ====== Pass 1: S = K·Q^T (n rows) -> D[n] -> vp = v/D B-frags =========== */
__global__ __launch_bounds__(256)
void pass1_kernel()
{
    __shared__ u32 qb[3][PA];
    __shared__ float Dsh[128];
    __shared__ float invd[128];

    const int t = threadIdx.x, w = t >> 5, lane = t & 31;
    const int g = lane >> 2, tg = lane & 3;
    const int b = blockIdx.y, nblk = blockIdx.x;

    /* K A-frags: warp w owns n-rows w*16..+15 */
    uint4 a[3];
    {
        const u32* kA = g_kA + (b*NB + nblk)*PA;
        #pragma unroll
        for (int ck = 0; ck < 3; ++ck)
            a[ck] = *(const uint4*)(kA + (w*3 + ck)*128 + lane*4);
    }

    const char* qsrc = (const char*)(g_qB + (long)b*NB*PA);
    {   /* prologue: chunks 0 and 1 as two groups */
        const u32 d0 = smem_u32(qb[0]);
        for (int i = t; i < 768; i += 256) cpa16(d0 + i*16, qsrc + i*16);
        CP_COMMIT();
        const u32 d1 = smem_u32(qb[1]);
        const char* s1 = qsrc + (long)PA*4;
        for (int i = t; i < 768; i += 256) cpa16(d1 + i*16, s1 + i*16);
        CP_COMMIT();
    }

    float rs0 = 0.f, rs1 = 0.f;
    int buf = 0;

    for (int mc = 0; mc < NB; ++mc){
        CP_WAIT1();
        __syncthreads();
        /* prefetch mc+2 (reuses buffer of mc-1, safe after barrier) */
        if (mc + 2 < NB){
            const int nb2 = (buf + 2 >= 3) ? buf - 1 : buf + 2;
            const u32 d = smem_u32(qb[nb2]);
            const char* s = qsrc + (long)(mc + 2)*PA*4;
            for (int i = t; i < 768; i += 256) cpa16(d + i*16, s + i*16);
        }
        CP_COMMIT();

        const u32* cur = qb[buf];
        #pragma unroll 4
        for (int ctb = 0; ctb < 16; ++ctb){
            float acc[4] = {0.f, 0.f, 0.f, 0.f};
            #pragma unroll
            for (int ck = 0; ck < 3; ++ck){
                const uint2 bq = *(const uint2*)(cur + (ctb*3 + ck)*64 + lane*2);
                mma_h(acc, a[ck], bq);
            }
            rs0 += ex2f(fminf(acc[0],15.f)) + ex2f(fminf(acc[1],15.f));
            rs1 += ex2f(fminf(acc[2],15.f)) + ex2f(fminf(acc[3],15.f));
        }
        buf = (buf + 1 >= 3) ? 0 : buf + 1;
    }

    /* reduce over m-col lanes (tg) -> D for rows w*16+g / +8+g */
    rs0 += __shfl_xor_sync(0xFFFFFFFFu, rs0, 1);
    rs0 += __shfl_xor_sync(0xFFFFFFFFu, rs0, 2);
    rs1 += __shfl_xor_sync(0xFFFFFFFFu, rs1, 1);
    rs1 += __shfl_xor_sync(0xFFFFFFFFu, rs1, 2);
    if (tg == 0){ Dsh[w*16 + g] = rs0; Dsh[w*16 + 8 + g] = rs1; }
    __syncthreads();
    if (t < 128) invd[t] = 1.0f / Dsh[t];
    __syncthreads();

    /* vp = v/D as B-frag panel */
    {
        u32* vdst = g_vB + (b*NB + nblk)*PA;
        const float* vb = g_v + (long)b*48*NN + nblk*128;
        for (int j = t; j < PA; j += 256){
            const int reg = j & 1, l5 = (j >> 1) & 31, tile = j >> 6;
            const int kk = tile/6, ct = tile - 6*kk;
            const int c  = ct*8 + (l5 >> 2);
            const int nl = kk*16 + (l5 & 3)*2 + reg*8;
            const float2 vv = *(const float2*)(vb + (long)c*NN + nl);
            vdst[j] = pkh(vv.x*invd[nl], vv.y*invd[nl + 1]);
        }
    }
}

/* ====== Pass 2: recompute S (m rows) -> P in regs -> PV -> out proj ====== */
__global__ __launch_bounds__(256)
void pass2_kernel(const float* __restrict__ wo, const float* __restrict__ bo,
                  float* __restrict__ out)
{
    extern __shared__ char smraw[];
    u32* sK = (u32*)smraw;                  /* [3][3072] u32 */
    u32* sV = sK + 3*PA;                    /* [3][3072] u32 */
    float* wo_s = (float*)(sV + 3*PA);      /* 432 */
    float* bo_s = wo_s + 432;               /* 12 + pad */
    float* attn = (float*)smraw;            /* 48*132 reuse after loop */

    const int t = threadIdx.x, w = t >> 5, lane = t & 31;
    const int g = lane >> 2, tg = lane & 3;
    const int b = blockIdx.y, mt = blockIdx.x;

    for (int i = t; i < 432; i += 256) wo_s[i] = wo[i];
    if (t < 12) bo_s[t] = bo[t];

    /* Q A-frags: warp w owns m-rows w*16..+15 */
    uint4 aq[3];
    {
        const u32* qA = g_qA + (b*NB + mt)*PA;
        #pragma unroll
        for (int ck = 0; ck < 3; ++ck)
            aq[ck] = *(const uint4*)(qA + (w*3 + ck)*128 + lane*4);
    }

    const char* ksrc = (const char*)(g_kB + (long)b*NB*PA);
    const char* vsrc = (const char*)(g_vB + (long)b*NB*PA);
    {   /* prologue: chunks 0 and 1 */
        const u32 dk0 = smem_u32(sK), dv0 = smem_u32(sV);
        for (int i = t; i < 768; i += 256){ cpa16(dk0 + i*16, ksrc + i*16); cpa16(dv0 + i*16, vsrc + i*16); }
        CP_COMMIT();
        const u32 dk1 = smem_u32(sK + PA), dv1 = smem_u32(sV + PA);
        const char* sk1 = ksrc + (long)PA*4;
        const char* sv1 = vsrc + (long)PA*4;
        for (int i = t; i < 768; i += 256){ cpa16(dk1 + i*16, sk1 + i*16); cpa16(dv1 + i*16, sv1 + i*16); }
        CP_COMMIT();
    }

    float acc2[6][4];
    #pragma unroll
    for (int ct = 0; ct < 6; ++ct)
        #pragma unroll
        for (int i = 0; i < 4; ++i) acc2[ct][i] = 0.f;

    int buf = 0;

    for (int nc = 0; nc < NB; ++nc){
        CP_WAIT1();
        __syncthreads();
        if (nc + 2 < NB){
            const int nb2 = (buf + 2 >= 3) ? buf - 1 : buf + 2;
            const u32 dk = smem_u32(sK + nb2*PA);
            const u32 dv = smem_u32(sV + nb2*PA);
            const char* sk = ksrc + (long)(nc + 2)*PA*4;
            const char* sv = vsrc + (long)(nc + 2)*PA*4;
            for (int i = t; i < 768; i += 256){ cpa16(dk + i*16, sk + i*16); cpa16(dv + i*16, sv + i*16); }
        }
        CP_COMMIT();

        const u32* curK = sK + buf*PA;
        const u32* curV = sV + buf*PA;

        /* software-pipelined: S(j+1) issues while exp(j)/PV(j) retire */
        float sa[2][8];
        {   /* S(0) */
            #pragma unroll
            for (int i = 0; i < 8; ++i) sa[0][i] = 0.f;
            #pragma unroll
            for (int ck = 0; ck < 3; ++ck){
                const uint2 b0 = *(const uint2*)(curK + (0*3 + ck)*64 + lane*2);
                const uint2 b1 = *(const uint2*)(curK + (1*3 + ck)*64 + lane*2);
                mma_h(sa[0],     aq[ck], b0);
                mma_h(sa[0] + 4, aq[ck], b1);
            }
        }
        #pragma unroll
        for (int j = 0; j < 8; ++j){
            const int pj = j & 1, nj = pj ^ 1;
            if (j < 7){
                #pragma unroll
                for (int i = 0; i < 8; ++i) sa[nj][i] = 0.f;
                #pragma unroll
                for (int ck = 0; ck < 3; ++ck){
                    const uint2 b0 = *(const uint2*)(curK + ((2*j + 2)*3 + ck)*64 + lane*2);
                    const uint2 b1 = *(const uint2*)(curK + ((2*j + 3)*3 + ck)*64 + lane*2);
                    mma_h(sa[nj],     aq[ck], b0);
                    mma_h(sa[nj] + 4, aq[ck], b1);
                }
            }
            uint4 pf;
            pf.x = pkh(ex2f(fminf(sa[pj][0],15.f)), ex2f(fminf(sa[pj][1],15.f)));
            pf.y = pkh(ex2f(fminf(sa[pj][2],15.f)), ex2f(fminf(sa[pj][3],15.f)));
            pf.z = pkh(ex2f(fminf(sa[pj][4],15.f)), ex2f(fminf(sa[pj][5],15.f)));
            pf.w = pkh(ex2f(fminf(sa[pj][6],15.f)), ex2f(fminf(sa[pj][7],15.f)));
            #pragma unroll
            for (int ct = 0; ct < 6; ++ct){
                const uint2 bv = *(const uint2*)(curV + (j*6 + ct)*64 + lane*2);
                mma_h(acc2[ct], pf, bv);
            }
        }
        buf = (buf + 1 >= 3) ? 0 : buf + 1;
    }

    /* drain pending copies, then reuse smem for attn staging */
    CP_WAIT0();
    __syncthreads();
    #pragma unroll
    for (int ct = 0; ct < 6; ++ct){
        const int m0 = w*16 + g, cb = ct*8 + 2*tg;
        attn[cb*132 + m0]           = acc2[ct][0];
        attn[(cb + 1)*132 + m0]     = acc2[ct][1];
        attn[cb*132 + m0 + 8]       = acc2[ct][2];
        attn[(cb + 1)*132 + m0 + 8] = acc2[ct][3];
    }
    __syncthreads();
    {
        const int og = t >> 7, m = t & 127;
        #pragma unroll
        for (int oo = 0; oo < 6; ++oo){
            const int o = og*6 + oo;
            float s = bo_s[o];
            #pragma unroll
            for (int c = 0; c < 36; ++c) s += wo_s[o*36 + c]*attn[c*132 + m];
            out[((long)(b*12 + o))*NN + mt*128 + m] = s;
        }
    }
}

/* ============================== launch =================================== */
extern "C" void kernel_launch(void* const* d_in, const int* in_sizes, int n_in,
                              void* d_out, int out_size)
{
    const float* x  = (const float*)d_in[0];
    const float* wq = (const float*)d_in[1];
    const float* bq = (const float*)d_in[2];
    const float* wk = (const float*)d_in[3];
    const float* bk = (const float*)d_in[4];
    const float* wv = (const float*)d_in[5];
    const float* bv = (const float*)d_in[6];
    const float* wo = (const float*)d_in[7];
    const float* bo = (const float*)d_in[8];
    float* out = (float*)d_out;

    /* pass2: 6*12288 + 432*4 + 64 = 75520 bytes dynamic smem */
    cudaFuncSetAttribute(pass2_kernel,
                         cudaFuncAttributeMaxDynamicSharedMemorySize, 75520);

    qkv_kernel  <<<dim3(NB, 8), 128>>>(x, wq, bq, wk, bk, wv, bv);
    pass1_kernel<<<dim3(NB, 8), 256>>>();
    pass2_kernel<<<dim3(NB, 8), 256, 75520>>>(wo, bo, out);
}

// round 8
// speedup vs baseline: 1.0577x; 1.0577x over previous
#include <cuda_runtime.h>
#include <cuda_fp16.h>
#include <cstdint>

#define NN 4096
#define NB 32
#define PA 3072      /* u32 per fragment panel: 128 rows/cols x 48 k fp16 pairs */
#define SCALE2 (0.28867513459481287f * 1.4426950408889634f)  /* (1/sqrt12)*log2e */

typedef unsigned int u32;

/* ---------------- global scratch ----------------------------------------- */
__device__ __align__(16) u32   g_qA[8*NB*PA];     /* Q as mma-A frags (pass2) */
__device__ __align__(16) u32   g_qB[8*NB*PA];     /* Q as mma-B frags (pass1) */
__device__ __align__(16) u32   g_kA[8*NB*PA];     /* K as mma-A frags (pass1) */
__device__ __align__(16) u32   g_kB[8*NB*PA];     /* K as mma-B frags (pass2) */
__device__ __align__(16) u32   g_vB[8*NB*PA];     /* v/D as mma-B frags (pass2) */
__device__ __align__(16) float g_v [8*48*NN];     /* fp32 v, rows 36..47 zero */

/* ---------------- helpers ------------------------------------------------ */
__device__ __forceinline__ void mma_h(float* d, uint4 a, uint2 b){
    asm("mma.sync.aligned.m16n8k16.row.col.f32.f16.f16.f32 "
        "{%0,%1,%2,%3},{%4,%5,%6,%7},{%8,%9},{%0,%1,%2,%3};"
        : "+f"(d[0]), "+f"(d[1]), "+f"(d[2]), "+f"(d[3])
        : "r"(a.x), "r"(a.y), "r"(a.z), "r"(a.w), "r"(b.x), "r"(b.y));
}
__device__ __forceinline__ u32 pkh(float lo, float hi){
    __half2 h = __floats2half2_rn(lo, hi);
    return *(u32*)&h;
}
/* pack two f32 into f16x2 (lo in low half) */
__device__ __forceinline__ u32 cvt2h(float lo, float hi){
    u32 r; asm("cvt.rn.f16x2.f32 %0, %1, %2;" : "=r"(r) : "f"(hi), "f"(lo));
    return r;
}
/* clamp to 15.5 and 2^x, both lanes, one MUFU op */
__device__ __forceinline__ u32 ex2h2(u32 x, u32 hmin){
    u32 r;
    asm("{\n\t.reg .b32 t;\n\tmin.f16x2 t, %1, %2;\n\tex2.approx.f16x2 %0, t;\n\t}"
        : "=r"(r) : "r"(x), "r"(hmin));
    return r;
}
__device__ __forceinline__ u32 smem_u32(const void* p){
    u32 a;
    asm("{ .reg .u64 t; cvta.to.shared.u64 t, %1; cvt.u32.u64 %0, t; }" : "=r"(a) : "l"(p));
    return a;
}
__device__ __forceinline__ void cpa16(u32 d, const void* s){
    asm volatile("cp.async.ca.shared.global [%0], [%1], 16;" :: "r"(d), "l"(s));
}
#define CP_COMMIT() asm volatile("cp.async.commit_group;")
#define CP_WAIT1()  asm volatile("cp.async.wait_group 1;")
#define CP_WAIT0()  asm volatile("cp.async.wait_group 0;")
#define HMIN_CONST 0x4BC04BC0u   /* {15.5h, 15.5h} */

/* ========== Kernel A: QKV -> panels; 3 warp-groups (q|k|v) =============== */
__global__ __launch_bounds__(384)
void qkv_kernel(const float* __restrict__ x,
                const float* __restrict__ wq, const float* __restrict__ bq,
                const float* __restrict__ wk, const float* __restrict__ bk,
                const float* __restrict__ wv, const float* __restrict__ bv)
{
    __shared__ float w_s[3*432];
    __shared__ float b_s[3*36];
    const int t = threadIdx.x;
    const int wg = t >> 7, tl = t & 127;
    const int b = blockIdx.y, nblk = blockIdx.x;
    const int n = nblk*128 + tl;

    const float* wsrc = (wg == 0) ? wq : (wg == 1) ? wk : wv;
    const float* bsrc = (wg == 0) ? bq : (wg == 1) ? bk : bv;
    for (int i = tl; i < 432; i += 128) w_s[wg*432 + i] = wsrc[i];
    if (tl < 36) b_s[wg*36 + tl] = bsrc[tl];
    __syncthreads();

    float xv[12];
    #pragma unroll
    for (int c = 0; c < 12; ++c) xv[c] = x[(b*12 + c)*NN + n];

    float ov[36];
    const float* w = w_s + wg*432;
    const float* bb = b_s + wg*36;
    #pragma unroll 4
    for (int o = 0; o < 36; ++o){
        float acc = bb[o];
        #pragma unroll
        for (int c = 0; c < 12; ++c) acc += w[o*12 + c]*xv[c];
        ov[o] = acc;
    }

    if (wg == 2){
        #pragma unroll 4
        for (int o = 0; o < 36; ++o) g_v[((long)(b*48+o))*NN + n] = ov[o];
        #pragma unroll
        for (int o = 36; o < 48; ++o) g_v[((long)(b*48+o))*NN + n] = 0.f;
        return;
    }
    if (wg == 0){
        #pragma unroll
        for (int o = 0; o < 36; ++o) ov[o] *= SCALE2;  /* fold scale + log2e */
    }

    u32* pA = (wg == 0) ? g_qA : g_kA;
    u32* pB = (wg == 0) ? g_qB : g_kB;
    const int base = (b*NB + nblk)*PA;
    const int rt = tl >> 4, lr = tl & 15;   /* A coords: row = tl */
    const int ct = tl >> 3, gB = tl & 7;    /* B coords: col = tl */

    #pragma unroll
    for (int p = 0; p < 24; ++p){
        const int kk = p >> 3, cp = p & 7;
        const int c0 = kk*16 + cp*2, c1 = c0 + 1;
        const float f0 = (c0 < 36) ? ov[c0] : 0.f, f1 = (c1 < 36) ? ov[c1] : 0.f;
        const u32 fp = pkh(f0, f1);
        const int regA  = ((cp >> 2) << 1) | (lr >> 3);
        const int laneA = ((lr & 7) << 2) | (cp & 3);
        pA[base + (rt*3 + kk)*128 + laneA*4 + regA] = fp;
        const int regB  = cp >> 2;
        const int laneB = (gB << 2) | (cp & 3);
        pB[base + (ct*3 + kk)*64 + laneB*2 + regB] = fp;
    }
}

/* ====== Pass 1: S = K·Q^T (n rows) -> D[n] -> vp = v/D B-frags =========== */
/* 512 thr: warp (wg = w>>1) owns n-rows wg*16..+15; h = w&1 owns m-half    */
__global__ __launch_bounds__(512, 1)
void pass1_kernel()
{
    __shared__ u32 qb[3][PA];
    __shared__ float Dsh[256];
    __shared__ float invd[128];

    const int t = threadIdx.x, w = t >> 5, lane = t & 31;
    const int wg = w >> 1, h = w & 1;
    const int g = lane >> 2, tg = lane & 3;
    const int b = blockIdx.y, nblk = blockIdx.x;
    const u32 hmin = HMIN_CONST;

    /* K A-frags: n-rows wg*16..+15 */
    uint4 a[3];
    {
        const u32* kA = g_kA + (b*NB + nblk)*PA;
        #pragma unroll
        for (int ck = 0; ck < 3; ++ck)
            a[ck] = *(const uint4*)(kA + (wg*3 + ck)*128 + lane*4);
    }

    const char* qsrc = (const char*)(g_qB + (long)b*NB*PA);
    {
        const u32 d0 = smem_u32(qb[0]);
        for (int i = t; i < 768; i += 512) cpa16(d0 + i*16, qsrc + i*16);
        CP_COMMIT();
        const u32 d1 = smem_u32(qb[1]);
        const char* s1 = qsrc + (long)PA*4;
        for (int i = t; i < 768; i += 512) cpa16(d1 + i*16, s1 + i*16);
        CP_COMMIT();
    }

    float rs0 = 0.f, rs1 = 0.f;
    int buf = 0;

    for (int mc = 0; mc < NB; ++mc){
        CP_WAIT1();
        __syncthreads();
        if (mc + 2 < NB){
            const int nb2 = (buf + 2 >= 3) ? buf - 1 : buf + 2;
            const u32 d = smem_u32(qb[nb2]);
            const char* s = qsrc + (long)(mc + 2)*PA*4;
            for (int i = t; i < 512; i += 512) ;   /* keep loop shape simple */
            for (int i = t; i < 768; i += 512) cpa16(d + i*16, s + i*16);
        }
        CP_COMMIT();

        const u32* cur = qb[buf];
        #pragma unroll
        for (int cl = 0; cl < 8; ++cl){
            const int ctb = h*8 + cl;
            float acc[4] = {0.f, 0.f, 0.f, 0.f};
            #pragma unroll
            for (int ck = 0; ck < 3; ++ck){
                const uint2 bq = *(const uint2*)(cur + (ctb*3 + ck)*64 + lane*2);
                mma_h(acc, a[ck], bq);
            }
            const u32 ea = ex2h2(cvt2h(acc[0], acc[1]), hmin);
            const u32 eb = ex2h2(cvt2h(acc[2], acc[3]), hmin);
            const float2 fa = __half22float2(*(const __half2*)&ea);
            const float2 fb = __half22float2(*(const __half2*)&eb);
            rs0 += fa.x + fa.y;
            rs1 += fb.x + fb.y;
        }
        buf = (buf + 1 >= 3) ? 0 : buf + 1;
    }

    /* reduce over m-col lanes (tg), then over halves via smem */
    rs0 += __shfl_xor_sync(0xFFFFFFFFu, rs0, 1);
    rs0 += __shfl_xor_sync(0xFFFFFFFFu, rs0, 2);
    rs1 += __shfl_xor_sync(0xFFFFFFFFu, rs1, 1);
    rs1 += __shfl_xor_sync(0xFFFFFFFFu, rs1, 2);
    if (tg == 0){
        Dsh[h*128 + wg*16 + g]     = rs0;
        Dsh[h*128 + wg*16 + 8 + g] = rs1;
    }
    __syncthreads();
    if (t < 128) invd[t] = 1.0f / (Dsh[t] + Dsh[128 + t]);
    __syncthreads();

    /* vp = v/D as B-frag panel */
    {
        u32* vdst = g_vB + (b*NB + nblk)*PA;
        const float* vb = g_v + (long)b*48*NN + nblk*128;
        for (int j = t; j < PA; j += 512){
            const int reg = j & 1, l5 = (j >> 1) & 31, tile = j >> 6;
            const int kk = tile/6, ct = tile - 6*kk;
            const int c  = ct*8 + (l5 >> 2);
            const int nl = kk*16 + (l5 & 3)*2 + reg*8;
            const float2 vv = *(const float2*)(vb + (long)c*NN + nl);
            vdst[j] = pkh(vv.x*invd[nl], vv.y*invd[nl + 1]);
        }
    }
}

/* ====== Pass 2: recompute S -> P (f16 regs) -> PV -> out projection ====== */
/* 512 thr: warp (wg = w>>1) owns m-rows wg*16..+15; h = w&1 owns n-half    */
__global__ __launch_bounds__(512, 1)
void pass2_kernel(const float* __restrict__ wo, const float* __restrict__ bo,
                  float* __restrict__ out)
{
    extern __shared__ char smraw[];
    u32* sK = (u32*)smraw;                  /* [3][3072] u32 */
    u32* sV = sK + 3*PA;                    /* [3][3072] u32 */
    float* wo_s = (float*)(sV + 3*PA);      /* 432 */
    float* bo_s = wo_s + 432;               /* 12 + pad */
    float* attn = (float*)smraw;            /* 48*132 reuse after loop */

    const int t = threadIdx.x, w = t >> 5, lane = t & 31;
    const int wg = w >> 1, h = w & 1;
    const int g = lane >> 2, tg = lane & 3;
    const int b = blockIdx.y, mt = blockIdx.x;
    const u32 hmin = HMIN_CONST;

    for (int i = t; i < 432; i += 512) wo_s[i] = wo[i];
    if (t < 12) bo_s[t] = bo[t];

    /* Q A-frags: m-rows wg*16..+15 */
    uint4 aq[3];
    {
        const u32* qA = g_qA + (b*NB + mt)*PA;
        #pragma unroll
        for (int ck = 0; ck < 3; ++ck)
            aq[ck] = *(const uint4*)(qA + (wg*3 + ck)*128 + lane*4);
    }

    const char* ksrc = (const char*)(g_kB + (long)b*NB*PA);
    const char* vsrc = (const char*)(g_vB + (long)b*NB*PA);
    {
        const u32 dk0 = smem_u32(sK), dv0 = smem_u32(sV);
        for (int i = t; i < 768; i += 512){ cpa16(dk0 + i*16, ksrc + i*16); cpa16(dv0 + i*16, vsrc + i*16); }
        CP_COMMIT();
        const u32 dk1 = smem_u32(sK + PA), dv1 = smem_u32(sV + PA);
        const char* sk1 = ksrc + (long)PA*4;
        const char* sv1 = vsrc + (long)PA*4;
        for (int i = t; i < 768; i += 512){ cpa16(dk1 + i*16, sk1 + i*16); cpa16(dv1 + i*16, sv1 + i*16); }
        CP_COMMIT();
    }

    float acc2[6][4];   /* partial over this warp's n-half */
    #pragma unroll
    for (int ct = 0; ct < 6; ++ct)
        #pragma unroll
        for (int i = 0; i < 4; ++i) acc2[ct][i] = 0.f;

    int buf = 0;

    for (int nc = 0; nc < NB; ++nc){
        CP_WAIT1();
        __syncthreads();
        if (nc + 2 < NB){
            const int nb2 = (buf + 2 >= 3) ? buf - 1 : buf + 2;
            const u32 dk = smem_u32(sK + nb2*PA);
            const u32 dv = smem_u32(sV + nb2*PA);
            const char* sk = ksrc + (long)(nc + 2)*PA*4;
            const char* sv = vsrc + (long)(nc + 2)*PA*4;
            for (int i = t; i < 768; i += 512){ cpa16(dk + i*16, sk + i*16); cpa16(dv + i*16, sv + i*16); }
        }
        CP_COMMIT();

        const u32* curK = sK + buf*PA;
        const u32* curV = sV + buf*PA;

        /* 4 k16 groups in this warp's n-half */
        #pragma unroll
        for (int j = 0; j < 4; ++j){
            const int ctb0 = h*8 + 2*j, ctb1 = ctb0 + 1;
            float a0[4] = {0.f,0.f,0.f,0.f}, a1[4] = {0.f,0.f,0.f,0.f};
            #pragma unroll
            for (int ck = 0; ck < 3; ++ck){
                const uint2 b0 = *(const uint2*)(curK + (ctb0*3 + ck)*64 + lane*2);
                const uint2 b1 = *(const uint2*)(curK + (ctb1*3 + ck)*64 + lane*2);
                mma_h(a0, aq[ck], b0);
                mma_h(a1, aq[ck], b1);
            }
            uint4 pf;
            pf.x = ex2h2(cvt2h(a0[0], a0[1]), hmin);
            pf.y = ex2h2(cvt2h(a0[2], a0[3]), hmin);
            pf.z = ex2h2(cvt2h(a1[0], a1[1]), hmin);
            pf.w = ex2h2(cvt2h(a1[2], a1[3]), hmin);
            const int kk = h*4 + j;
            #pragma unroll
            for (int ct = 0; ct < 6; ++ct){
                const uint2 bv = *(const uint2*)(curV + (kk*6 + ct)*64 + lane*2);
                mma_h(acc2[ct], pf, bv);
            }
        }
        buf = (buf + 1 >= 3) ? 0 : buf + 1;
    }

    /* drain copies, stage attn (h=0 writes, h=1 adds), project */
    CP_WAIT0();
    __syncthreads();
    if (h == 0){
        #pragma unroll
        for (int ct = 0; ct < 6; ++ct){
            const int m0 = wg*16 + g, cb = ct*8 + 2*tg;
            attn[cb*132 + m0]           = acc2[ct][0];
            attn[(cb + 1)*132 + m0]     = acc2[ct][1];
            attn[cb*132 + m0 + 8]       = acc2[ct][2];
            attn[(cb + 1)*132 + m0 + 8] = acc2[ct][3];
        }
    }
    __syncthreads();
    if (h == 1){
        #pragma unroll
        for (int ct = 0; ct < 6; ++ct){
            const int m0 = wg*16 + g, cb = ct*8 + 2*tg;
            attn[cb*132 + m0]           += acc2[ct][0];
            attn[(cb + 1)*132 + m0]     += acc2[ct][1];
            attn[cb*132 + m0 + 8]       += acc2[ct][2];
            attn[(cb + 1)*132 + m0 + 8] += acc2[ct][3];
        }
    }
    __syncthreads();
    {
        const int og = t >> 7, m = t & 127;
        #pragma unroll
        for (int oo = 0; oo < 3; ++oo){
            const int o = og*3 + oo;
            float s = bo_s[o];
            #pragma unroll
            for (int c = 0; c < 36; ++c) s += wo_s[o*36 + c]*attn[c*132 + m];
            out[((long)(b*12 + o))*NN + mt*128 + m] = s;
        }
    }
}

/* ============================== launch =================================== */
extern "C" void kernel_launch(void* const* d_in, const int* in_sizes, int n_in,
                              void* d_out, int out_size)
{
    const float* x  = (const float*)d_in[0];
    const float* wq = (const float*)d_in[1];
    const float* bq = (const float*)d_in[2];
    const float* wk = (const float*)d_in[3];
    const float* bk = (const float*)d_in[4];
    const float* wv = (const float*)d_in[5];
    const float* bv = (const float*)d_in[6];
    const float* wo = (const float*)d_in[7];
    const float* bo = (const float*)d_in[8];
    float* out = (float*)d_out;

    /* pass2: 6*12288 + 432*4 + 64 = 75520 bytes dynamic smem */
    cudaFuncSetAttribute(pass2_kernel,
                         cudaFuncAttributeMaxDynamicSharedMemorySize, 75520);

    qkv_kernel  <<<dim3(NB, 8), 384>>>(x, wq, bq, wk, bk, wv, bv);
    pass1_kernel<<<dim3(NB, 8), 512>>>();
    pass2_kernel<<<dim3(NB, 8), 512, 75520>>>(wo, bo, out);
}

// round 10
// speedup vs baseline: 1.1574x; 1.0943x over previous
#include <cuda_runtime.h>
#include <cuda_fp16.h>
#include <cstdint>

#define NN 4096
#define NB 32
#define PA 3072      /* u32 per fragment panel: 128 rows/cols x 48 k fp16 pairs */
#define SCALE2 (0.28867513459481287f * 1.4426950408889634f)  /* (1/sqrt12)*log2e */

typedef unsigned int u32;

/* ---------------- global scratch ----------------------------------------- */
__device__ __align__(16) u32   g_qA[8*NB*PA];     /* Q as mma-A frags (pass2) */
__device__ __align__(16) u32   g_qB[8*NB*PA];     /* Q as mma-B frags (pass1) */
__device__ __align__(16) u32   g_kA[8*NB*PA];     /* K as mma-A frags (pass1) */
__device__ __align__(16) u32   g_kB[8*NB*PA];     /* K as mma-B frags (pass2) */
__device__ __align__(16) u32   g_vB[8*NB*PA];     /* v/D as mma-B frags (pass2) */
__device__ __align__(16) float g_v [8*48*NN];     /* fp32 v, rows 36..47 zero */

/* ---------------- helpers ------------------------------------------------ */
__device__ __forceinline__ void mma_h(float* d, uint4 a, uint2 b){
    asm("mma.sync.aligned.m16n8k16.row.col.f32.f16.f16.f32 "
        "{%0,%1,%2,%3},{%4,%5,%6,%7},{%8,%9},{%0,%1,%2,%3};"
        : "+f"(d[0]), "+f"(d[1]), "+f"(d[2]), "+f"(d[3])
        : "r"(a.x), "r"(a.y), "r"(a.z), "r"(a.w), "r"(b.x), "r"(b.y));
}
__device__ __forceinline__ u32 pkh(float lo, float hi){
    __half2 h = __floats2half2_rn(lo, hi);
    return *(u32*)&h;
}
__device__ __forceinline__ u32 cvt2h(float lo, float hi){
    u32 r; asm("cvt.rn.f16x2.f32 %0, %1, %2;" : "=r"(r) : "f"(hi), "f"(lo));
    return r;
}
__device__ __forceinline__ u32 ex2h2(u32 x, u32 hmin){
    u32 r;
    asm("{\n\t.reg .b32 t;\n\tmin.f16x2 t, %1, %2;\n\tex2.approx.f16x2 %0, t;\n\t}"
        : "=r"(r) : "r"(x), "r"(hmin));
    return r;
}
__device__ __forceinline__ u32 smem_u32(const void* p){
    u32 a;
    asm("{ .reg .u64 t; cvta.to.shared.u64 t, %1; cvt.u32.u64 %0, t; }" : "=r"(a) : "l"(p));
    return a;
}
__device__ __forceinline__ void cpa16(u32 d, const void* s){
    asm volatile("cp.async.ca.shared.global [%0], [%1], 16;" :: "r"(d), "l"(s));
}
#define CP_COMMIT() asm volatile("cp.async.commit_group;")
#define CP_WAIT1()  asm volatile("cp.async.wait_group 1;")
#define CP_WAIT0()  asm volatile("cp.async.wait_group 0;")
#define HMIN_CONST 0x4BC04BC0u   /* {15.5h, 15.5h} */

/* ========== Kernel A: QKV -> panels; 3 warp-groups (q|k|v) =============== */
__global__ __launch_bounds__(384)
void qkv_kernel(const float* __restrict__ x,
                const float* __restrict__ wq, const float* __restrict__ bq,
                const float* __restrict__ wk, const float* __restrict__ bk,
                const float* __restrict__ wv, const float* __restrict__ bv)
{
    __shared__ __align__(16) float w_s[3*432];
    __shared__ __align__(16) float b_s[3*36];
    const int t = threadIdx.x;
    const int wg = t >> 7, tl = t & 127;
    const int b = blockIdx.y, nblk = blockIdx.x;
    const int n = nblk*128 + tl;

    const float* wsrc = (wg == 0) ? wq : (wg == 1) ? wk : wv;
    const float* bsrc = (wg == 0) ? bq : (wg == 1) ? bk : bv;
    for (int i = tl; i < 432; i += 128) w_s[wg*432 + i] = wsrc[i];
    if (tl < 36) b_s[wg*36 + tl] = bsrc[tl];
    __syncthreads();

    float xv[12];
    #pragma unroll
    for (int c = 0; c < 12; ++c) xv[c] = x[(b*12 + c)*NN + n];

    float ov[36];
    const float* w = w_s + wg*432;
    const float* bb = b_s + wg*36;
    #pragma unroll 4
    for (int o = 0; o < 36; ++o){
        float acc = bb[o];
        #pragma unroll
        for (int c = 0; c < 12; ++c) acc += w[o*12 + c]*xv[c];
        ov[o] = acc;
    }

    if (wg == 2){
        #pragma unroll 4
        for (int o = 0; o < 36; ++o) g_v[((long)(b*48+o))*NN + n] = ov[o];
        #pragma unroll
        for (int o = 36; o < 48; ++o) g_v[((long)(b*48+o))*NN + n] = 0.f;
        return;
    }
    if (wg == 0){
        #pragma unroll
        for (int o = 0; o < 36; ++o) ov[o] *= SCALE2;
    }

    u32* pA = (wg == 0) ? g_qA : g_kA;
    u32* pB = (wg == 0) ? g_qB : g_kB;
    const int base = (b*NB + nblk)*PA;
    const int rt = tl >> 4, lr = tl & 15;
    const int ct = tl >> 3, gB = tl & 7;

    #pragma unroll
    for (int p = 0; p < 24; ++p){
        const int kk = p >> 3, cp = p & 7;
        const int c0 = kk*16 + cp*2, c1 = c0 + 1;
        const float f0 = (c0 < 36) ? ov[c0] : 0.f, f1 = (c1 < 36) ? ov[c1] : 0.f;
        const u32 fp = pkh(f0, f1);
        const int regA  = ((cp >> 2) << 1) | (lr >> 3);
        const int laneA = ((lr & 7) << 2) | (cp & 3);
        pA[base + (rt*3 + kk)*128 + laneA*4 + regA] = fp;
        const int regB  = cp >> 2;
        const int laneB = (gB << 2) | (cp & 3);
        pB[base + (ct*3 + kk)*64 + laneB*2 + regB] = fp;
    }
}

/* ====== Pass 1: S = K·Q^T -> D[n] -> vp = v/D B-frags ==================== */
/* 512 thr = 16 warps: wg = w>>2 owns n-rows wg*32..+31 (2 A-tiles);
   h = w&3 owns m-quarter. Each B-frag load feeds 2 mma.                    */
__global__ __launch_bounds__(512)
void pass1_kernel()
{
    __shared__ __align__(16) u32 qb[3][PA];
    __shared__ __align__(16) float Dsh[512];
    __shared__ __align__(16) float invd[128];

    const int t = threadIdx.x, w = t >> 5, lane = t & 31;
    const int wg = w >> 2, h = w & 3;
    const int g = lane >> 2, tg = lane & 3;
    const int b = blockIdx.y, nblk = blockIdx.x;
    const u32 hmin = HMIN_CONST;

    /* K A-frags: 2 tiles (n-rows wg*32..+31) */
    uint4 a0f[3], a1f[3];
    {
        const u32* kA = g_kA + (b*NB + nblk)*PA;
        #pragma unroll
        for (int ck = 0; ck < 3; ++ck){
            a0f[ck] = *(const uint4*)(kA + ((wg*2 + 0)*3 + ck)*128 + lane*4);
            a1f[ck] = *(const uint4*)(kA + ((wg*2 + 1)*3 + ck)*128 + lane*4);
        }
    }

    const char* qsrc = (const char*)(g_qB + (long)b*NB*PA);
    {
        const u32 d0 = smem_u32(&qb[0][0]);
        for (int i = t; i < 768; i += 512) cpa16(d0 + i*16, qsrc + i*16);
        CP_COMMIT();
        const u32 d1 = smem_u32(&qb[1][0]);
        const char* s1 = qsrc + (long)PA*4;
        for (int i = t; i < 768; i += 512) cpa16(d1 + i*16, s1 + i*16);
        CP_COMMIT();
    }

    float rs00 = 0.f, rs01 = 0.f, rs10 = 0.f, rs11 = 0.f;
    int buf = 0;

    for (int mc = 0; mc < NB; ++mc){
        CP_WAIT1();
        __syncthreads();
        if (mc + 2 < NB){
            const int nb2 = (buf + 2 >= 3) ? buf - 1 : buf + 2;
            const u32 d = smem_u32(&qb[nb2][0]);
            const char* s = qsrc + (long)(mc + 2)*PA*4;
            for (int i = t; i < 768; i += 512) cpa16(d + i*16, s + i*16);
        }
        CP_COMMIT();

        const u32* cur = &qb[buf][0];
        #pragma unroll
        for (int cl = 0; cl < 4; ++cl){
            const int ctb = h*4 + cl;
            uint2 bq0 = *(const uint2*)(cur + (ctb*3 + 0)*64 + lane*2);
            uint2 bq1 = *(const uint2*)(cur + (ctb*3 + 1)*64 + lane*2);
            uint2 bq2 = *(const uint2*)(cur + (ctb*3 + 2)*64 + lane*2);
            {
                float acc[4] = {0.f, 0.f, 0.f, 0.f};
                mma_h(acc, a0f[0], bq0); mma_h(acc, a0f[1], bq1); mma_h(acc, a0f[2], bq2);
                const u32 ea = ex2h2(cvt2h(acc[0], acc[1]), hmin);
                const u32 eb = ex2h2(cvt2h(acc[2], acc[3]), hmin);
                const float2 fa = __half22float2(*(const __half2*)&ea);
                const float2 fb = __half22float2(*(const __half2*)&eb);
                rs00 += fa.x + fa.y;
                rs01 += fb.x + fb.y;
            }
            {
                float acc[4] = {0.f, 0.f, 0.f, 0.f};
                mma_h(acc, a1f[0], bq0); mma_h(acc, a1f[1], bq1); mma_h(acc, a1f[2], bq2);
                const u32 ea = ex2h2(cvt2h(acc[0], acc[1]), hmin);
                const u32 eb = ex2h2(cvt2h(acc[2], acc[3]), hmin);
                const float2 fa = __half22float2(*(const __half2*)&ea);
                const float2 fb = __half22float2(*(const __half2*)&eb);
                rs10 += fa.x + fa.y;
                rs11 += fb.x + fb.y;
            }
        }
        buf = (buf + 1 >= 3) ? 0 : buf + 1;
    }

    /* reduce over m-col lanes (tg); stage per-quarter in Dsh[h*128 + row] */
    rs00 += __shfl_xor_sync(0xFFFFFFFFu, rs00, 1);
    rs00 += __shfl_xor_sync(0xFFFFFFFFu, rs00, 2);
    rs01 += __shfl_xor_sync(0xFFFFFFFFu, rs01, 1);
    rs01 += __shfl_xor_sync(0xFFFFFFFFu, rs01, 2);
    rs10 += __shfl_xor_sync(0xFFFFFFFFu, rs10, 1);
    rs10 += __shfl_xor_sync(0xFFFFFFFFu, rs10, 2);
    rs11 += __shfl_xor_sync(0xFFFFFFFFu, rs11, 1);
    rs11 += __shfl_xor_sync(0xFFFFFFFFu, rs11, 2);
    if (tg == 0){
        Dsh[h*128 + wg*32 + g]      = rs00;
        Dsh[h*128 + wg*32 + 8 + g]  = rs01;
        Dsh[h*128 + wg*32 + 16 + g] = rs10;
        Dsh[h*128 + wg*32 + 24 + g] = rs11;
    }
    __syncthreads();
    if (t < 128) invd[t] = 1.0f / (Dsh[t] + Dsh[128 + t] + Dsh[256 + t] + Dsh[384 + t]);
    __syncthreads();

    /* vp = v/D as B-frag panel (verbatim from R8) */
    {
        u32* vdst = g_vB + (b*NB + nblk)*PA;
        const float* vb = g_v + (long)b*48*NN + nblk*128;
        for (int j = t; j < PA; j += 512){
            const int reg = j & 1, l5 = (j >> 1) & 31, tile = j >> 6;
            const int kk = tile/6, ct = tile - 6*kk;
            const int c  = ct*8 + (l5 >> 2);
            const int nl = kk*16 + (l5 & 3)*2 + reg*8;
            const float2 vv = *(const float2*)(vb + (long)c*NN + nl);
            vdst[j] = pkh(vv.x*invd[nl], vv.y*invd[nl + 1]);
        }
    }
}

/* ====== Pass 2: recompute S -> P (f16) -> PV -> out projection =========== */
/* 512 thr = 16 warps: wg = w>>2 owns m-rows wg*32..+31 (2 A-tiles);
   h = w&3 owns n-quarter (k16 groups h*2, h*2+1).                          */
__global__ __launch_bounds__(512)
void pass2_kernel(const float* __restrict__ wo, const float* __restrict__ bo,
                  float* __restrict__ out)
{
    extern __shared__ __align__(16) char smraw[];
    u32* sK = (u32*)smraw;                  /* [3][3072] u32 */
    u32* sV = sK + 3*PA;                    /* [3][3072] u32 */
    float* wo_s = (float*)(sV + 3*PA);      /* 432 */
    float* bo_s = wo_s + 432;               /* 12 + pad */
    float* attn = (float*)smraw;            /* 48*132 floats, reuse after loop */

    const int t = threadIdx.x, w = t >> 5, lane = t & 31;
    const int wg = w >> 2, h = w & 3;
    const int g = lane >> 2, tg = lane & 3;
    const int b = blockIdx.y, mt = blockIdx.x;
    const u32 hmin = HMIN_CONST;

    for (int i = t; i < 432; i += 512) wo_s[i] = wo[i];
    if (t < 12) bo_s[t] = bo[t];

    /* Q A-frags: 2 tiles (m-rows wg*32..+31) */
    uint4 aq0[3], aq1[3];
    {
        const u32* qA = g_qA + (b*NB + mt)*PA;
        #pragma unroll
        for (int ck = 0; ck < 3; ++ck){
            aq0[ck] = *(const uint4*)(qA + ((wg*2 + 0)*3 + ck)*128 + lane*4);
            aq1[ck] = *(const uint4*)(qA + ((wg*2 + 1)*3 + ck)*128 + lane*4);
        }
    }

    const char* ksrc = (const char*)(g_kB + (long)b*NB*PA);
    const char* vsrc = (const char*)(g_vB + (long)b*NB*PA);
    {
        const u32 dk0 = smem_u32(sK), dv0 = smem_u32(sV);
        for (int i = t; i < 768; i += 512){ cpa16(dk0 + i*16, ksrc + i*16); cpa16(dv0 + i*16, vsrc + i*16); }
        CP_COMMIT();
        const u32 dk1 = smem_u32(sK + PA), dv1 = smem_u32(sV + PA);
        const char* sk1 = ksrc + (long)PA*4;
        const char* sv1 = vsrc + (long)PA*4;
        for (int i = t; i < 768; i += 512){ cpa16(dk1 + i*16, sk1 + i*16); cpa16(dv1 + i*16, sv1 + i*16); }
        CP_COMMIT();
    }

    float accA[6][4], accB[6][4];   /* PV partials for A-tile 0 / 1 */
    #pragma unroll
    for (int ct = 0; ct < 6; ++ct)
        #pragma unroll
        for (int i = 0; i < 4; ++i){ accA[ct][i] = 0.f; accB[ct][i] = 0.f; }

    int buf = 0;

    for (int nc = 0; nc < NB; ++nc){
        CP_WAIT1();
        __syncthreads();
        if (nc + 2 < NB){
            const int nb2 = (buf + 2 >= 3) ? buf - 1 : buf + 2;
            const u32 dk = smem_u32(sK + nb2*PA);
            const u32 dv = smem_u32(sV + nb2*PA);
            const char* sk = ksrc + (long)(nc + 2)*PA*4;
            const char* sv = vsrc + (long)(nc + 2)*PA*4;
            for (int i = t; i < 768; i += 512){ cpa16(dk + i*16, sk + i*16); cpa16(dv + i*16, sv + i*16); }
        }
        CP_COMMIT();

        const u32* curK = sK + buf*PA;
        const u32* curV = sV + buf*PA;

        #pragma unroll
        for (int jj = 0; jj < 2; ++jj){
            const int kk = h*2 + jj;
            const int ctb0 = 2*kk, ctb1 = 2*kk + 1;
            /* B-frag loads, each reused by both A-tiles */
            uint2 b00 = *(const uint2*)(curK + (ctb0*3 + 0)*64 + lane*2);
            uint2 b01 = *(const uint2*)(curK + (ctb0*3 + 1)*64 + lane*2);
            uint2 b02 = *(const uint2*)(curK + (ctb0*3 + 2)*64 + lane*2);
            uint2 b10 = *(const uint2*)(curK + (ctb1*3 + 0)*64 + lane*2);
            uint2 b11 = *(const uint2*)(curK + (ctb1*3 + 1)*64 + lane*2);
            uint2 b12 = *(const uint2*)(curK + (ctb1*3 + 2)*64 + lane*2);
            uint2 bv0 = *(const uint2*)(curV + (kk*6 + 0)*64 + lane*2);
            uint2 bv1 = *(const uint2*)(curV + (kk*6 + 1)*64 + lane*2);
            uint2 bv2 = *(const uint2*)(curV + (kk*6 + 2)*64 + lane*2);
            uint2 bv3 = *(const uint2*)(curV + (kk*6 + 3)*64 + lane*2);
            uint2 bv4 = *(const uint2*)(curV + (kk*6 + 4)*64 + lane*2);
            uint2 bv5 = *(const uint2*)(curV + (kk*6 + 5)*64 + lane*2);

            {   /* A-tile 0: S -> pf -> PV */
                float s0[4] = {0.f,0.f,0.f,0.f}, s1[4] = {0.f,0.f,0.f,0.f};
                mma_h(s0, aq0[0], b00); mma_h(s0, aq0[1], b01); mma_h(s0, aq0[2], b02);
                mma_h(s1, aq0[0], b10); mma_h(s1, aq0[1], b11); mma_h(s1, aq0[2], b12);
                uint4 pf;
                pf.x = ex2h2(cvt2h(s0[0], s0[1]), hmin);
                pf.y = ex2h2(cvt2h(s0[2], s0[3]), hmin);
                pf.z = ex2h2(cvt2h(s1[0], s1[1]), hmin);
                pf.w = ex2h2(cvt2h(s1[2], s1[3]), hmin);
                mma_h(accA[0], pf, bv0); mma_h(accA[1], pf, bv1); mma_h(accA[2], pf, bv2);
                mma_h(accA[3], pf, bv3); mma_h(accA[4], pf, bv4); mma_h(accA[5], pf, bv5);
            }
            {   /* A-tile 1 */
                float s0[4] = {0.f,0.f,0.f,0.f}, s1[4] = {0.f,0.f,0.f,0.f};
                mma_h(s0, aq1[0], b00); mma_h(s0, aq1[1], b01); mma_h(s0, aq1[2], b02);
                mma_h(s1, aq1[0], b10); mma_h(s1, aq1[1], b11); mma_h(s1, aq1[2], b12);
                uint4 pf;
                pf.x = ex2h2(cvt2h(s0[0], s0[1]), hmin);
                pf.y = ex2h2(cvt2h(s0[2], s0[3]), hmin);
                pf.z = ex2h2(cvt2h(s1[0], s1[1]), hmin);
                pf.w = ex2h2(cvt2h(s1[2], s1[3]), hmin);
                mma_h(accB[0], pf, bv0); mma_h(accB[1], pf, bv1); mma_h(accB[2], pf, bv2);
                mma_h(accB[3], pf, bv3); mma_h(accB[4], pf, bv4); mma_h(accB[5], pf, bv5);
            }
        }
        buf = (buf + 1 >= 3) ? 0 : buf + 1;
    }

    /* drain copies; 4 serialized accumulate phases into one attn buffer */
    CP_WAIT0();
    __syncthreads();
    #pragma unroll
    for (int ph = 0; ph < 4; ++ph){
        if (h == ph){
            #pragma unroll
            for (int ct = 0; ct < 6; ++ct){
                const int mA = wg*32 + g, mB = mA + 16, cb = ct*8 + 2*tg;
                if (ph == 0){
                    attn[cb*132 + mA]           = accA[ct][0];
                    attn[(cb + 1)*132 + mA]     = accA[ct][1];
                    attn[cb*132 + mA + 8]       = accA[ct][2];
                    attn[(cb + 1)*132 + mA + 8] = accA[ct][3];
                    attn[cb*132 + mB]           = accB[ct][0];
                    attn[(cb + 1)*132 + mB]     = accB[ct][1];
                    attn[cb*132 + mB + 8]       = accB[ct][2];
                    attn[(cb + 1)*132 + mB + 8] = accB[ct][3];
                } else {
                    attn[cb*132 + mA]           += accA[ct][0];
                    attn[(cb + 1)*132 + mA]     += accA[ct][1];
                    attn[cb*132 + mA + 8]       += accA[ct][2];
                    attn[(cb + 1)*132 + mA + 8] += accA[ct][3];
                    attn[cb*132 + mB]           += accB[ct][0];
                    attn[(cb + 1)*132 + mB]     += accB[ct][1];
                    attn[cb*132 + mB + 8]       += accB[ct][2];
                    attn[(cb + 1)*132 + mB + 8] += accB[ct][3];
                }
            }
        }
        __syncthreads();
    }

    /* output projection */
    {
        const int og = t >> 7, m = t & 127;
        #pragma unroll
        for (int oo = 0; oo < 3; ++oo){
            const int o = og*3 + oo;
            float s = bo_s[o];
            #pragma unroll
            for (int c = 0; c < 36; ++c) s += wo_s[o*36 + c]*attn[c*132 + m];
            out[((long)(b*12 + o))*NN + mt*128 + m] = s;
        }
    }
}

/* ============================== launch =================================== */
extern "C" void kernel_launch(void* const* d_in, const int* in_sizes, int n_in,
                              void* d_out, int out_size)
{
    const float* x  = (const float*)d_in[0];
    const float* wq = (const float*)d_in[1];
    const float* bq = (const float*)d_in[2];
    const float* wk = (const float*)d_in[3];
    const float* bk = (const float*)d_in[4];
    const float* wv = (const float*)d_in[5];
    const float* bv = (const float*)d_in[6];
    const float* wo = (const float*)d_in[7];
    const float* bo = (const float*)d_in[8];
    float* out = (float*)d_out;

    /* pass2: 6*12288 + 432*4 + 64 = 75520 bytes dynamic smem */
    cudaFuncSetAttribute(pass2_kernel,
                         cudaFuncAttributeMaxDynamicSharedMemorySize, 75520);

    qkv_kernel  <<<dim3(NB, 8), 384>>>(x, wq, bq, wk, bk, wv, bv);
    pass1_kernel<<<dim3(NB, 8), 512>>>();
    pass2_kernel<<<dim3(NB, 8), 512, 75520>>>(wo, bo, out);
}

// round 11
// speedup vs baseline: 1.3124x; 1.1339x over previous
#include <cuda_runtime.h>
#include <cuda_fp16.h>
#include <cstdint>

#define NN 4096
#define NB 32
#define PA 3072      /* u32 per fragment panel: 128 rows/cols x 48 k fp16 pairs */
#define PW 1024      /* u32 per vw B-frag panel: 16 ch x 128 n fp16 */
#define SCALE2 (0.28867513459481287f * 1.4426950408889634f)  /* (1/sqrt12)*log2e */

typedef unsigned int u32;

/* ---------------- global scratch ----------------------------------------- */
__device__ __align__(16) u32   g_qA[8*NB*PA];     /* Q as mma-A frags (pass2) */
__device__ __align__(16) u32   g_qB[8*NB*PA];     /* Q as mma-B frags (pass1) */
__device__ __align__(16) u32   g_kA[8*NB*PA];     /* K as mma-A frags (pass1) */
__device__ __align__(16) u32   g_kB[8*NB*PA];     /* K as mma-B frags (pass2) */
__device__ __align__(16) u32   g_vw[8*NB*PW];     /* wo·(v/D) as B-frags     */
__device__ __align__(16) float g_v [8*48*NN];     /* fp32 v, rows 36..47 zero */

/* ---------------- helpers ------------------------------------------------ */
__device__ __forceinline__ void mma_h(float* d, uint4 a, uint2 b){
    asm("mma.sync.aligned.m16n8k16.row.col.f32.f16.f16.f32 "
        "{%0,%1,%2,%3},{%4,%5,%6,%7},{%8,%9},{%0,%1,%2,%3};"
        : "+f"(d[0]), "+f"(d[1]), "+f"(d[2]), "+f"(d[3])
        : "r"(a.x), "r"(a.y), "r"(a.z), "r"(a.w), "r"(b.x), "r"(b.y));
}
__device__ __forceinline__ u32 pkh(float lo, float hi){
    __half2 h = __floats2half2_rn(lo, hi);
    return *(u32*)&h;
}
__device__ __forceinline__ u32 cvt2h(float lo, float hi){
    u32 r; asm("cvt.rn.f16x2.f32 %0, %1, %2;" : "=r"(r) : "f"(hi), "f"(lo));
    return r;
}
__device__ __forceinline__ u32 ex2h2(u32 x, u32 hmin){
    u32 r;
    asm("{\n\t.reg .b32 t;\n\tmin.f16x2 t, %1, %2;\n\tex2.approx.f16x2 %0, t;\n\t}"
        : "=r"(r) : "r"(x), "r"(hmin));
    return r;
}
__device__ __forceinline__ u32 smem_u32(const void* p){
    u32 a;
    asm("{ .reg .u64 t; cvta.to.shared.u64 t, %1; cvt.u32.u64 %0, t; }" : "=r"(a) : "l"(p));
    return a;
}
__device__ __forceinline__ void cpa16(u32 d, const void* s){
    asm volatile("cp.async.ca.shared.global [%0], [%1], 16;" :: "r"(d), "l"(s));
}
#define CP_COMMIT() asm volatile("cp.async.commit_group;")
#define CP_WAIT1()  asm volatile("cp.async.wait_group 1;")
#define CP_WAIT0()  asm volatile("cp.async.wait_group 0;")
#define HMIN_CONST 0x4BC04BC0u   /* {15.5h, 15.5h} */

/* ========== Kernel A: QKV -> panels; 3 warp-groups (q|k|v) =============== */
__global__ __launch_bounds__(384)
void qkv_kernel(const float* __restrict__ x,
                const float* __restrict__ wq, const float* __restrict__ bq,
                const float* __restrict__ wk, const float* __restrict__ bk,
                const float* __restrict__ wv, const float* __restrict__ bv)
{
    __shared__ __align__(16) float w_s[3*432];
    __shared__ __align__(16) float b_s[3*36];
    const int t = threadIdx.x;
    const int wg = t >> 7, tl = t & 127;
    const int b = blockIdx.y, nblk = blockIdx.x;
    const int n = nblk*128 + tl;

    const float* wsrc = (wg == 0) ? wq : (wg == 1) ? wk : wv;
    const float* bsrc = (wg == 0) ? bq : (wg == 1) ? bk : bv;
    for (int i = tl; i < 432; i += 128) w_s[wg*432 + i] = wsrc[i];
    if (tl < 36) b_s[wg*36 + tl] = bsrc[tl];
    __syncthreads();

    float xv[12];
    #pragma unroll
    for (int c = 0; c < 12; ++c) xv[c] = x[(b*12 + c)*NN + n];

    float ov[36];
    const float* w = w_s + wg*432;
    const float* bb = b_s + wg*36;
    #pragma unroll 4
    for (int o = 0; o < 36; ++o){
        float acc = bb[o];
        #pragma unroll
        for (int c = 0; c < 12; ++c) acc += w[o*12 + c]*xv[c];
        ov[o] = acc;
    }

    if (wg == 2){
        #pragma unroll 4
        for (int o = 0; o < 36; ++o) g_v[((long)(b*48+o))*NN + n] = ov[o];
        #pragma unroll
        for (int o = 36; o < 48; ++o) g_v[((long)(b*48+o))*NN + n] = 0.f;
        return;
    }
    if (wg == 0){
        #pragma unroll
        for (int o = 0; o < 36; ++o) ov[o] *= SCALE2;
    }

    u32* pA = (wg == 0) ? g_qA : g_kA;
    u32* pB = (wg == 0) ? g_qB : g_kB;
    const int base = (b*NB + nblk)*PA;
    const int rt = tl >> 4, lr = tl & 15;
    const int ct = tl >> 3, gB = tl & 7;

    #pragma unroll
    for (int p = 0; p < 24; ++p){
        const int kk = p >> 3, cp = p & 7;
        const int c0 = kk*16 + cp*2, c1 = c0 + 1;
        const float f0 = (c0 < 36) ? ov[c0] : 0.f, f1 = (c1 < 36) ? ov[c1] : 0.f;
        const u32 fp = pkh(f0, f1);
        const int regA  = ((cp >> 2) << 1) | (lr >> 3);
        const int laneA = ((lr & 7) << 2) | (cp & 3);
        pA[base + (rt*3 + kk)*128 + laneA*4 + regA] = fp;
        const int regB  = cp >> 2;
        const int laneB = (gB << 2) | (cp & 3);
        pB[base + (ct*3 + kk)*64 + laneB*2 + regB] = fp;
    }
}

/* ====== Pass 1: S = K·Q^T -> D[n] -> vw = wo·(v/D) B-frags =============== */
/* 512 thr = 16 warps: wg = w>>2 owns n-rows wg*32..+31 (2 A-tiles);
   h = w&3 owns m-quarter. Each B-frag load feeds 2 mma.                    */
__global__ __launch_bounds__(512)
void pass1_kernel(const float* __restrict__ wo)
{
    __shared__ __align__(16) u32 qb[3][PA];
    __shared__ __align__(16) float Dsh[512];
    __shared__ __align__(16) float invd[128];
    __shared__ __align__(16) float wo_s[432];

    const int t = threadIdx.x, w = t >> 5, lane = t & 31;
    const int wg = w >> 2, h = w & 3;
    const int g = lane >> 2, tg = lane & 3;
    const int b = blockIdx.y, nblk = blockIdx.x;
    const u32 hmin = HMIN_CONST;

    for (int i = t; i < 432; i += 512) wo_s[i] = wo[i];

    /* K A-frags: 2 tiles (n-rows wg*32..+31) */
    uint4 a0f[3], a1f[3];
    {
        const u32* kA = g_kA + (b*NB + nblk)*PA;
        #pragma unroll
        for (int ck = 0; ck < 3; ++ck){
            a0f[ck] = *(const uint4*)(kA + ((wg*2 + 0)*3 + ck)*128 + lane*4);
            a1f[ck] = *(const uint4*)(kA + ((wg*2 + 1)*3 + ck)*128 + lane*4);
        }
    }

    const char* qsrc = (const char*)(g_qB + (long)b*NB*PA);
    {
        const u32 d0 = smem_u32(&qb[0][0]);
        for (int i = t; i < 768; i += 512) cpa16(d0 + i*16, qsrc + i*16);
        CP_COMMIT();
        const u32 d1 = smem_u32(&qb[1][0]);
        const char* s1 = qsrc + (long)PA*4;
        for (int i = t; i < 768; i += 512) cpa16(d1 + i*16, s1 + i*16);
        CP_COMMIT();
    }

    float rs00 = 0.f, rs01 = 0.f, rs10 = 0.f, rs11 = 0.f;
    int buf = 0;

    for (int mc = 0; mc < NB; ++mc){
        CP_WAIT1();
        __syncthreads();
        if (mc + 2 < NB){
            const int nb2 = (buf + 2 >= 3) ? buf - 1 : buf + 2;
            const u32 d = smem_u32(&qb[nb2][0]);
            const char* s = qsrc + (long)(mc + 2)*PA*4;
            for (int i = t; i < 768; i += 512) cpa16(d + i*16, s + i*16);
        }
        CP_COMMIT();

        const u32* cur = &qb[buf][0];
        #pragma unroll
        for (int cl = 0; cl < 4; ++cl){
            const int ctb = h*4 + cl;
            uint2 bq0 = *(const uint2*)(cur + (ctb*3 + 0)*64 + lane*2);
            uint2 bq1 = *(const uint2*)(cur + (ctb*3 + 1)*64 + lane*2);
            uint2 bq2 = *(const uint2*)(cur + (ctb*3 + 2)*64 + lane*2);
            {
                float acc[4] = {0.f, 0.f, 0.f, 0.f};
                mma_h(acc, a0f[0], bq0); mma_h(acc, a0f[1], bq1); mma_h(acc, a0f[2], bq2);
                const u32 ea = ex2h2(cvt2h(acc[0], acc[1]), hmin);
                const u32 eb = ex2h2(cvt2h(acc[2], acc[3]), hmin);
                const float2 fa = __half22float2(*(const __half2*)&ea);
                const float2 fb = __half22float2(*(const __half2*)&eb);
                rs00 += fa.x + fa.y;
                rs01 += fb.x + fb.y;
            }
            {
                float acc[4] = {0.f, 0.f, 0.f, 0.f};
                mma_h(acc, a1f[0], bq0); mma_h(acc, a1f[1], bq1); mma_h(acc, a1f[2], bq2);
                const u32 ea = ex2h2(cvt2h(acc[0], acc[1]), hmin);
                const u32 eb = ex2h2(cvt2h(acc[2], acc[3]), hmin);
                const float2 fa = __half22float2(*(const __half2*)&ea);
                const float2 fb = __half22float2(*(const __half2*)&eb);
                rs10 += fa.x + fa.y;
                rs11 += fb.x + fb.y;
            }
        }
        buf = (buf + 1 >= 3) ? 0 : buf + 1;
    }

    /* reduce over m-col lanes (tg); stage per-quarter in Dsh[h*128 + row] */
    rs00 += __shfl_xor_sync(0xFFFFFFFFu, rs00, 1);
    rs00 += __shfl_xor_sync(0xFFFFFFFFu, rs00, 2);
    rs01 += __shfl_xor_sync(0xFFFFFFFFu, rs01, 1);
    rs01 += __shfl_xor_sync(0xFFFFFFFFu, rs01, 2);
    rs10 += __shfl_xor_sync(0xFFFFFFFFu, rs10, 1);
    rs10 += __shfl_xor_sync(0xFFFFFFFFu, rs10, 2);
    rs11 += __shfl_xor_sync(0xFFFFFFFFu, rs11, 1);
    rs11 += __shfl_xor_sync(0xFFFFFFFFu, rs11, 2);
    if (tg == 0){
        Dsh[h*128 + wg*32 + g]      = rs00;
        Dsh[h*128 + wg*32 + 8 + g]  = rs01;
        Dsh[h*128 + wg*32 + 16 + g] = rs10;
        Dsh[h*128 + wg*32 + 24 + g] = rs11;
    }
    __syncthreads();
    if (t < 128) invd[t] = 1.0f / (Dsh[t] + Dsh[128 + t] + Dsh[256 + t] + Dsh[384 + t]);
    /* drain pending cp.async before reusing qb as scratch */
    CP_WAIT0();
    __syncthreads();

    /* ---- vw = wo · (v/D): stage v chunk, compute, write B-frag panel ---- */
    float* vstage = (float*)&qb[0][0];       /* 36*128 floats = 18KB */
    float* vw_s   = vstage + 36*128;         /* 16*128 floats =  8KB */
    {
        const float* vb = g_v + (long)b*48*NN + nblk*128;
        for (int idx = t; idx < 36*128; idx += 512){
            const int c = idx >> 7, n = idx & 127;
            vstage[idx] = vb[(long)c*NN + n];
        }
    }
    __syncthreads();
    for (int idx = t; idx < 2048; idx += 512){
        const int o = idx >> 7, n = idx & 127;
        float s = 0.f;
        if (o < 12){
            const float* wrow = wo_s + o*36;
            #pragma unroll 4
            for (int c = 0; c < 36; ++c) s += wrow[c]*vstage[c*128 + n];
            s *= invd[n];
        }
        vw_s[idx] = s;
    }
    __syncthreads();
    {
        u32* vdst = g_vw + (b*NB + nblk)*PW;
        for (int j = t; j < PW; j += 512){
            const int reg = j & 1, l5 = (j >> 1) & 31, tile = j >> 6;
            const int kk = tile >> 1, ct = tile & 1;
            const int o = ct*8 + (l5 >> 2);
            const int n = kk*16 + (l5 & 3)*2 + reg*8;
            vdst[j] = pkh(vw_s[o*128 + n], vw_s[o*128 + n + 1]);
        }
    }
}

/* ====== Pass 2: recompute S -> P (f16) -> P·vw^T = out rows ============== */
/* 512 thr = 16 warps: wg = w>>2 owns m-rows wg*32..+31 (2 A-tiles);
   h = w&3 owns n-quarter (k16 groups h*2, h*2+1).                          */
__global__ __launch_bounds__(512)
void pass2_kernel(const float* __restrict__ bo, float* __restrict__ out)
{
    extern __shared__ __align__(16) char smraw[];
    u32* sK  = (u32*)smraw;                 /* [3][3072] u32 */
    u32* sW  = sK + 3*PA;                   /* [3][1024] u32 */
    float* bo_s = (float*)(sW + 3*PW);      /* 16 floats */
    float* outb = (float*)smraw;            /* 16*132 floats, reuse after loop */

    const int t = threadIdx.x, w = t >> 5, lane = t & 31;
    const int wg = w >> 2, h = w & 3;
    const int g = lane >> 2, tg = lane & 3;
    const int b = blockIdx.y, mt = blockIdx.x;
    const u32 hmin = HMIN_CONST;

    if (t < 12) bo_s[t] = bo[t];

    /* Q A-frags: 2 tiles (m-rows wg*32..+31) */
    uint4 aq0[3], aq1[3];
    {
        const u32* qA = g_qA + (b*NB + mt)*PA;
        #pragma unroll
        for (int ck = 0; ck < 3; ++ck){
            aq0[ck] = *(const uint4*)(qA + ((wg*2 + 0)*3 + ck)*128 + lane*4);
            aq1[ck] = *(const uint4*)(qA + ((wg*2 + 1)*3 + ck)*128 + lane*4);
        }
    }

    const char* ksrc = (const char*)(g_kB + (long)b*NB*PA);
    const char* wsrc = (const char*)(g_vw + (long)b*NB*PW);
    {
        const u32 dk0 = smem_u32(sK), dw0 = smem_u32(sW);
        for (int i = t; i < 768; i += 512) cpa16(dk0 + i*16, ksrc + i*16);
        if (t < 256) cpa16(dw0 + t*16, wsrc + t*16);
        CP_COMMIT();
        const u32 dk1 = smem_u32(sK + PA), dw1 = smem_u32(sW + PW);
        const char* sk1 = ksrc + (long)PA*4;
        const char* sw1 = wsrc + (long)PW*4;
        for (int i = t; i < 768; i += 512) cpa16(dk1 + i*16, sk1 + i*16);
        if (t < 256) cpa16(dw1 + t*16, sw1 + t*16);
        CP_COMMIT();
    }

    float accA[2][4], accB[2][4];   /* out partials: [ct][frag] per A-tile */
    #pragma unroll
    for (int ct = 0; ct < 2; ++ct)
        #pragma unroll
        for (int i = 0; i < 4; ++i){ accA[ct][i] = 0.f; accB[ct][i] = 0.f; }

    int buf = 0;

    for (int nc = 0; nc < NB; ++nc){
        CP_WAIT1();
        __syncthreads();
        if (nc + 2 < NB){
            const int nb2 = (buf + 2 >= 3) ? buf - 1 : buf + 2;
            const u32 dk = smem_u32(sK + nb2*PA);
            const u32 dw = smem_u32(sW + nb2*PW);
            const char* sk = ksrc + (long)(nc + 2)*PA*4;
            const char* sw = wsrc + (long)(nc + 2)*PW*4;
            for (int i = t; i < 768; i += 512) cpa16(dk + i*16, sk + i*16);
            if (t < 256) cpa16(dw + t*16, sw + t*16);
        }
        CP_COMMIT();

        const u32* curK = sK + buf*PA;
        const u32* curW = sW + buf*PW;

        #pragma unroll
        for (int jj = 0; jj < 2; ++jj){
            const int kk = h*2 + jj;
            const int ctb0 = 2*kk, ctb1 = 2*kk + 1;
            uint2 b00 = *(const uint2*)(curK + (ctb0*3 + 0)*64 + lane*2);
            uint2 b01 = *(const uint2*)(curK + (ctb0*3 + 1)*64 + lane*2);
            uint2 b02 = *(const uint2*)(curK + (ctb0*3 + 2)*64 + lane*2);
            uint2 b10 = *(const uint2*)(curK + (ctb1*3 + 0)*64 + lane*2);
            uint2 b11 = *(const uint2*)(curK + (ctb1*3 + 1)*64 + lane*2);
            uint2 b12 = *(const uint2*)(curK + (ctb1*3 + 2)*64 + lane*2);
            uint2 bw0 = *(const uint2*)(curW + (kk*2 + 0)*64 + lane*2);
            uint2 bw1 = *(const uint2*)(curW + (kk*2 + 1)*64 + lane*2);

            {   /* A-tile 0: S -> pf -> out += pf x vw */
                float s0[4] = {0.f,0.f,0.f,0.f}, s1[4] = {0.f,0.f,0.f,0.f};
                mma_h(s0, aq0[0], b00); mma_h(s0, aq0[1], b01); mma_h(s0, aq0[2], b02);
                mma_h(s1, aq0[0], b10); mma_h(s1, aq0[1], b11); mma_h(s1, aq0[2], b12);
                uint4 pf;
                pf.x = ex2h2(cvt2h(s0[0], s0[1]), hmin);
                pf.y = ex2h2(cvt2h(s0[2], s0[3]), hmin);
                pf.z = ex2h2(cvt2h(s1[0], s1[1]), hmin);
                pf.w = ex2h2(cvt2h(s1[2], s1[3]), hmin);
                mma_h(accA[0], pf, bw0);
                mma_h(accA[1], pf, bw1);
            }
            {   /* A-tile 1 */
                float s0[4] = {0.f,0.f,0.f,0.f}, s1[4] = {0.f,0.f,0.f,0.f};
                mma_h(s0, aq1[0], b00); mma_h(s0, aq1[1], b01); mma_h(s0, aq1[2], b02);
                mma_h(s1, aq1[0], b10); mma_h(s1, aq1[1], b11); mma_h(s1, aq1[2], b12);
                uint4 pf;
                pf.x = ex2h2(cvt2h(s0[0], s0[1]), hmin);
                pf.y = ex2h2(cvt2h(s0[2], s0[3]), hmin);
                pf.z = ex2h2(cvt2h(s1[0], s1[1]), hmin);
                pf.w = ex2h2(cvt2h(s1[2], s1[3]), hmin);
                mma_h(accB[0], pf, bw0);
                mma_h(accB[1], pf, bw1);
            }
        }
        buf = (buf + 1 >= 3) ? 0 : buf + 1;
    }

    /* drain copies; 4 serialized accumulate phases into outb[16][132] */
    CP_WAIT0();
    __syncthreads();
    #pragma unroll
    for (int ph = 0; ph < 4; ++ph){
        if (h == ph){
            #pragma unroll
            for (int ct = 0; ct < 2; ++ct){
                const int mA = wg*32 + g, mB = mA + 16, cb = ct*8 + 2*tg;
                if (ph == 0){
                    outb[cb*132 + mA]           = accA[ct][0];
                    outb[(cb + 1)*132 + mA]     = accA[ct][1];
                    outb[cb*132 + mA + 8]       = accA[ct][2];
                    outb[(cb + 1)*132 + mA + 8] = accA[ct][3];
                    outb[cb*132 + mB]           = accB[ct][0];
                    outb[(cb + 1)*132 + mB]     = accB[ct][1];
                    outb[cb*132 + mB + 8]       = accB[ct][2];
                    outb[(cb + 1)*132 + mB + 8] = accB[ct][3];
                } else {
                    outb[cb*132 + mA]           += accA[ct][0];
                    outb[(cb + 1)*132 + mA]     += accA[ct][1];
                    outb[cb*132 + mA + 8]       += accA[ct][2];
                    outb[(cb + 1)*132 + mA + 8] += accA[ct][3];
                    outb[cb*132 + mB]           += accB[ct][0];
                    outb[(cb + 1)*132 + mB]     += accB[ct][1];
                    outb[cb*132 + mB + 8]       += accB[ct][2];
                    outb[(cb + 1)*132 + mB + 8] += accB[ct][3];
                }
            }
        }
        __syncthreads();
    }

    /* write out: 12 x 128 */
    {
        const int og = t >> 7, m = t & 127;
        #pragma unroll
        for (int oo = 0; oo < 3; ++oo){
            const int o = og*3 + oo;
            out[((long)(b*12 + o))*NN + mt*128 + m] = outb[o*132 + m] + bo_s[o];
        }
    }
}

/* ============================== launch =================================== */
extern "C" void kernel_launch(void* const* d_in, const int* in_sizes, int n_in,
                              void* d_out, int out_size)
{
    const float* x  = (const float*)d_in[0];
    const float* wq = (const float*)d_in[1];
    const float* bq = (const float*)d_in[2];
    const float* wk = (const float*)d_in[3];
    const float* bk = (const float*)d_in[4];
    const float* wv = (const float*)d_in[5];
    const float* bv = (const float*)d_in[6];
    const float* wo = (const float*)d_in[7];
    const float* bo = (const float*)d_in[8];
    float* out = (float*)d_out;

    /* pass2 dyn smem: 3*PA*4 + 3*PW*4 + 64 = 36864 + 12288 + 64 = 49216 */
    cudaFuncSetAttribute(pass2_kernel,
                         cudaFuncAttributeMaxDynamicSharedMemorySize, 49216);

    qkv_kernel  <<<dim3(NB, 8), 384>>>(x, wq, bq, wk, bk, wv, bv);
    pass1_kernel<<<dim3(NB, 8), 512>>>(wo);
    pass2_kernel<<<dim3(NB, 8), 512, 49216>>>(bo, out);
}

// round 13
// speedup vs baseline: 1.3890x; 1.0584x over previous
#include <cuda_runtime.h>
#include <cuda_fp16.h>
#include <cstdint>

#define NN 4096
#define NB 32
#define PA 3072      /* u32 per fragment panel: 128 rows/cols x 48 k fp16 pairs */
#define PW 1024      /* u32 per vw B-frag panel: 16 ch x 128 n fp16 */
#define SCALE2 (0.28867513459481287f * 1.4426950408889634f)  /* (1/sqrt12)*log2e */

typedef unsigned int u32;

/* ---------------- global scratch ----------------------------------------- */
__device__ __align__(16) u32   g_qA[8*NB*PA];     /* Q as mma-A frags (pass2) */
__device__ __align__(16) u32   g_qB[8*NB*PA];     /* Q as mma-B frags (pass1) */
__device__ __align__(16) u32   g_kA[8*NB*PA];     /* K as mma-A frags (pass1) */
__device__ __align__(16) u32   g_kB[8*NB*PA];     /* K as mma-B frags (pass2) */
__device__ __align__(16) u32   g_vw[8*NB*PW];     /* wo·(v/D) as B-frags     */
__device__ __align__(16) float g_v [8*48*NN];     /* fp32 v, rows 36..47 zero */

/* ---------------- helpers ------------------------------------------------ */
/* fp32-accumulate mma (PV only) */
__device__ __forceinline__ void mma_h(float* d, uint4 a, uint2 b){
    asm("mma.sync.aligned.m16n8k16.row.col.f32.f16.f16.f32 "
        "{%0,%1,%2,%3},{%4,%5,%6,%7},{%8,%9},{%0,%1,%2,%3};"
        : "+f"(d[0]), "+f"(d[1]), "+f"(d[2]), "+f"(d[3])
        : "r"(a.x), "r"(a.y), "r"(a.z), "r"(a.w), "r"(b.x), "r"(b.y));
}
/* fp16-accumulate mma (S computation: output already f16x2 pairs) */
__device__ __forceinline__ void mma_h16(u32* d, uint4 a, uint2 b){
    asm("mma.sync.aligned.m16n8k16.row.col.f16.f16.f16.f16 "
        "{%0,%1},{%2,%3,%4,%5},{%6,%7},{%0,%1};"
        : "+r"(d[0]), "+r"(d[1])
        : "r"(a.x), "r"(a.y), "r"(a.z), "r"(a.w), "r"(b.x), "r"(b.y));
}
__device__ __forceinline__ u32 pkh(float lo, float hi){
    __half2 h = __floats2half2_rn(lo, hi);
    return *(u32*)&h;
}
__device__ __forceinline__ u32 ex2h2(u32 x, u32 hmin){
    u32 r;
    asm("{\n\t.reg .b32 t;\n\tmin.f16x2 t, %1, %2;\n\tex2.approx.f16x2 %0, t;\n\t}"
        : "=r"(r) : "r"(x), "r"(hmin));
    return r;
}
__device__ __forceinline__ u32 smem_u32(const void* p){
    u32 a;
    asm("{ .reg .u64 t; cvta.to.shared.u64 t, %1; cvt.u32.u64 %0, t; }" : "=r"(a) : "l"(p));
    return a;
}
__device__ __forceinline__ void cpa16(u32 d, const void* s){
    asm volatile("cp.async.ca.shared.global [%0], [%1], 16;" :: "r"(d), "l"(s));
}
#define CP_COMMIT() asm volatile("cp.async.commit_group;")
#define CP_WAIT1()  asm volatile("cp.async.wait_group 1;")
#define CP_WAIT0()  asm volatile("cp.async.wait_group 0;")
#define HMIN_CONST 0x4BC04BC0u   /* {15.5h, 15.5h} */

/* ========== Kernel A: QKV -> smem-staged panels; 3 warp-groups =========== */
/* dyn smem layout: stage[12288 u32] | w_s[1296 f] | b_s[108 f] = 54768 B    */
__global__ __launch_bounds__(384)
void qkv_kernel(const float* __restrict__ x,
                const float* __restrict__ wq, const float* __restrict__ bq,
                const float* __restrict__ wk, const float* __restrict__ bk,
                const float* __restrict__ wv, const float* __restrict__ bv)
{
    extern __shared__ __align__(16) u32 dynq[];
    u32* stage = dynq;                       /* 12288 u32 = 48KB */
    float* w_s = (float*)(dynq + 12288);     /* 3*432 */
    float* b_s = w_s + 3*432;                /* 3*36  */

    const int t = threadIdx.x;
    const int wg = t >> 7, tl = t & 127;
    const int b = blockIdx.y, nblk = blockIdx.x;
    const int n = nblk*128 + tl;

    const float* wsrc = (wg == 0) ? wq : (wg == 1) ? wk : wv;
    const float* bsrc = (wg == 0) ? bq : (wg == 1) ? bk : bv;
    for (int i = tl; i < 432; i += 128) w_s[wg*432 + i] = wsrc[i];
    if (tl < 36) b_s[wg*36 + tl] = bsrc[tl];
    __syncthreads();

    float xv[12];
    #pragma unroll
    for (int c = 0; c < 12; ++c) xv[c] = x[(b*12 + c)*NN + n];

    float ov[36];
    const float* w = w_s + wg*432;
    const float* bb = b_s + wg*36;
    #pragma unroll 4
    for (int o = 0; o < 36; ++o){
        float acc = bb[o];
        #pragma unroll
        for (int c = 0; c < 12; ++c) acc += w[o*12 + c]*xv[c];
        ov[o] = acc;
    }

    if (wg == 2){
        #pragma unroll 4
        for (int o = 0; o < 36; ++o) g_v[((long)(b*48+o))*NN + n] = ov[o];
        #pragma unroll
        for (int o = 36; o < 48; ++o) g_v[((long)(b*48+o))*NN + n] = 0.f;
    } else {
        if (wg == 0){
            #pragma unroll
            for (int o = 0; o < 36; ++o) ov[o] *= SCALE2;   /* fold scale+log2e */
        }
        /* scatter into smem stage: [qA|qB|kA|kB], 3072 u32 each */
        u32* sA = stage + wg*6144;
        u32* sB = sA + 3072;
        const int rt = tl >> 4, lr = tl & 15;
        const int ct = tl >> 3, gB = tl & 7;
        #pragma unroll
        for (int p = 0; p < 24; ++p){
            const int kk = p >> 3, cp = p & 7;
            const int c0 = kk*16 + cp*2, c1 = c0 + 1;
            const float f0 = (c0 < 36) ? ov[c0] : 0.f, f1 = (c1 < 36) ? ov[c1] : 0.f;
            const u32 fp = pkh(f0, f1);
            const int regA  = ((cp >> 2) << 1) | (lr >> 3);
            const int laneA = ((lr & 7) << 2) | (cp & 3);
            sA[(rt*3 + kk)*128 + laneA*4 + regA] = fp;
            const int regB  = cp >> 2;
            const int laneB = (gB << 2) | (cp & 3);
            sB[(ct*3 + kk)*64 + laneB*2 + regB] = fp;
        }
    }
    __syncthreads();

    /* coalesced block copy: 3072 uint4 -> 4 gmem panels */
    {
        const int base4 = ((b*NB + nblk)*PA) >> 2;   /* uint4 index */
        const uint4* s4 = (const uint4*)stage;
        for (int i = t; i < 3072; i += 384){
            const int seg = i/768, off = i - seg*768;
            uint4* dst = (seg == 0) ? (uint4*)g_qA : (seg == 1) ? (uint4*)g_qB
                       : (seg == 2) ? (uint4*)g_kA : (uint4*)g_kB;
            dst[base4 + off] = s4[i];
        }
    }
}

/* ====== Pass 1: S = K·Q^T (f16 accum) -> D[n] -> vw = wo·(v/D) =========== */
/* 512 thr = 16 warps: wg = w>>2 owns n-rows wg*32..+31 (2 A-tiles);
   h = w&3 owns m-quarter. Each B-frag load feeds 2 mma.                    */
__global__ __launch_bounds__(512)
void pass1_kernel(const float* __restrict__ wo)
{
    __shared__ __align__(16) u32 qb[3][PA];
    __shared__ __align__(16) float Dsh[512];
    __shared__ __align__(16) float invd[128];
    __shared__ __align__(16) float wo_s[432];

    const int t = threadIdx.x, w = t >> 5, lane = t & 31;
    const int wg = w >> 2, h = w & 3;
    const int g = lane >> 2, tg = lane & 3;
    const int b = blockIdx.y, nblk = blockIdx.x;
    const u32 hmin = HMIN_CONST;

    for (int i = t; i < 432; i += 512) wo_s[i] = wo[i];

    /* K A-frags: 2 tiles (n-rows wg*32..+31) */
    uint4 a0f[3], a1f[3];
    {
        const u32* kA = g_kA + (b*NB + nblk)*PA;
        #pragma unroll
        for (int ck = 0; ck < 3; ++ck){
            a0f[ck] = *(const uint4*)(kA + ((wg*2 + 0)*3 + ck)*128 + lane*4);
            a1f[ck] = *(const uint4*)(kA + ((wg*2 + 1)*3 + ck)*128 + lane*4);
        }
    }

    const char* qsrc = (const char*)(g_qB + (long)b*NB*PA);
    {
        const u32 d0 = smem_u32(&qb[0][0]);
        for (int i = t; i < 768; i += 512) cpa16(d0 + i*16, qsrc + i*16);
        CP_COMMIT();
        const u32 d1 = smem_u32(&qb[1][0]);
        const char* s1 = qsrc + (long)PA*4;
        for (int i = t; i < 768; i += 512) cpa16(d1 + i*16, s1 + i*16);
        CP_COMMIT();
    }

    float rs00 = 0.f, rs01 = 0.f, rs10 = 0.f, rs11 = 0.f;
    int buf = 0;

    for (int mc = 0; mc < NB; ++mc){
        CP_WAIT1();
        __syncthreads();
        if (mc + 2 < NB){
            const int nb2 = (buf + 2 >= 3) ? buf - 1 : buf + 2;
            const u32 d = smem_u32(&qb[nb2][0]);
            const char* s = qsrc + (long)(mc + 2)*PA*4;
            for (int i = t; i < 768; i += 512) cpa16(d + i*16, s + i*16);
        }
        CP_COMMIT();

        const u32* cur = &qb[buf][0];
        #pragma unroll
        for (int cl = 0; cl < 4; ++cl){
            const int ctb = h*4 + cl;
            uint2 bq0 = *(const uint2*)(cur + (ctb*3 + 0)*64 + lane*2);
            uint2 bq1 = *(const uint2*)(cur + (ctb*3 + 1)*64 + lane*2);
            uint2 bq2 = *(const uint2*)(cur + (ctb*3 + 2)*64 + lane*2);
            {
                u32 s[2] = {0u, 0u};
                mma_h16(s, a0f[0], bq0); mma_h16(s, a0f[1], bq1); mma_h16(s, a0f[2], bq2);
                const u32 ea = ex2h2(s[0], hmin);
                const u32 eb = ex2h2(s[1], hmin);
                const float2 fa = __half22float2(*(const __half2*)&ea);
                const float2 fb = __half22float2(*(const __half2*)&eb);
                rs00 += fa.x + fa.y;
                rs01 += fb.x + fb.y;
            }
            {
                u32 s[2] = {0u, 0u};
                mma_h16(s, a1f[0], bq0); mma_h16(s, a1f[1], bq1); mma_h16(s, a1f[2], bq2);
                const u32 ea = ex2h2(s[0], hmin);
                const u32 eb = ex2h2(s[1], hmin);
                const float2 fa = __half22float2(*(const __half2*)&ea);
                const float2 fb = __half22float2(*(const __half2*)&eb);
                rs10 += fa.x + fa.y;
                rs11 += fb.x + fb.y;
            }
        }
        buf = (buf + 1 >= 3) ? 0 : buf + 1;
    }

    /* reduce over m-col lanes (tg); stage per-quarter in Dsh[h*128 + row] */
    rs00 += __shfl_xor_sync(0xFFFFFFFFu, rs00, 1);
    rs00 += __shfl_xor_sync(0xFFFFFFFFu, rs00, 2);
    rs01 += __shfl_xor_sync(0xFFFFFFFFu, rs01, 1);
    rs01 += __shfl_xor_sync(0xFFFFFFFFu, rs01, 2);
    rs10 += __shfl_xor_sync(0xFFFFFFFFu, rs10, 1);
    rs10 += __shfl_xor_sync(0xFFFFFFFFu, rs10, 2);
    rs11 += __shfl_xor_sync(0xFFFFFFFFu, rs11, 1);
    rs11 += __shfl_xor_sync(0xFFFFFFFFu, rs11, 2);
    if (tg == 0){
        Dsh[h*128 + wg*32 + g]      = rs00;
        Dsh[h*128 + wg*32 + 8 + g]  = rs01;
        Dsh[h*128 + wg*32 + 16 + g] = rs10;
        Dsh[h*128 + wg*32 + 24 + g] = rs11;
    }
    __syncthreads();
    if (t < 128) invd[t] = 1.0f / (Dsh[t] + Dsh[128 + t] + Dsh[256 + t] + Dsh[384 + t]);
    /* drain pending cp.async before reusing qb as scratch */
    CP_WAIT0();
    __syncthreads();

    /* ---- vw = wo · (v/D): stage v chunk, compute, write B-frag panel ---- */
    float* vstage = (float*)&qb[0][0];       /* 36*128 floats = 18KB */
    float* vw_s   = vstage + 36*128;         /* 16*128 floats =  8KB */
    {
        const float* vb = g_v + (long)b*48*NN + nblk*128;
        for (int idx = t; idx < 36*128; idx += 512){
            const int c = idx >> 7, n = idx & 127;
            vstage[idx] = vb[(long)c*NN + n];
        }
    }
    __syncthreads();
    for (int idx = t; idx < 2048; idx += 512){
        const int o = idx >> 7, n = idx & 127;
        float s = 0.f;
        if (o < 12){
            const float* wrow = wo_s + o*36;
            #pragma unroll 4
            for (int c = 0; c < 36; ++c) s += wrow[c]*vstage[c*128 + n];
            s *= invd[n];
        }
        vw_s[idx] = s;
    }
    __syncthreads();
    {
        u32* vdst = g_vw + (b*NB + nblk)*PW;
        for (int j = t; j < PW; j += 512){
            const int reg = j & 1, l5 = (j >> 1) & 31, tile = j >> 6;
            const int kk = tile >> 1, ct = tile & 1;
            const int o = ct*8 + (l5 >> 2);
            const int n = kk*16 + (l5 & 3)*2 + reg*8;
            vdst[j] = pkh(vw_s[o*128 + n], vw_s[o*128 + n + 1]);
        }
    }
}

/* ====== Pass 2: S (f16 accum) -> P -> P·vw^T (f32 accum) = out =========== */
/* 512 thr = 16 warps: wg = w>>2 owns m-rows wg*32..+31 (2 A-tiles);
   h = w&3 owns n-quarter (k16 groups h*2, h*2+1).                          */
__global__ __launch_bounds__(512)
void pass2_kernel(const float* __restrict__ bo, float* __restrict__ out)
{
    extern __shared__ __align__(16) char smraw[];
    u32* sK  = (u32*)smraw;                 /* [3][3072] u32 */
    u32* sW  = sK + 3*PA;                   /* [3][1024] u32 */
    float* bo_s = (float*)(sW + 3*PW);      /* 16 floats */
    float* outb = (float*)smraw;            /* 16*132 floats, reuse after loop */

    const int t = threadIdx.x, w = t >> 5, lane = t & 31;
    const int wg = w >> 2, h = w & 3;
    const int g = lane >> 2, tg = lane & 3;
    const int b = blockIdx.y, mt = blockIdx.x;
    const u32 hmin = HMIN_CONST;

    if (t < 12) bo_s[t] = bo[t];

    /* Q A-frags: 2 tiles (m-rows wg*32..+31) */
    uint4 aq0[3], aq1[3];
    {
        const u32* qA = g_qA + (b*NB + mt)*PA;
        #pragma unroll
        for (int ck = 0; ck < 3; ++ck){
            aq0[ck] = *(const uint4*)(qA + ((wg*2 + 0)*3 + ck)*128 + lane*4);
            aq1[ck] = *(const uint4*)(qA + ((wg*2 + 1)*3 + ck)*128 + lane*4);
        }
    }

    const char* ksrc = (const char*)(g_kB + (long)b*NB*PA);
    const char* wsrc = (const char*)(g_vw + (long)b*NB*PW);
    {
        const u32 dk0 = smem_u32(sK), dw0 = smem_u32(sW);
        for (int i = t; i < 768; i += 512) cpa16(dk0 + i*16, ksrc + i*16);
        if (t < 256) cpa16(dw0 + t*16, wsrc + t*16);
        CP_COMMIT();
        const u32 dk1 = smem_u32(sK + PA), dw1 = smem_u32(sW + PW);
        const char* sk1 = ksrc + (long)PA*4;
        const char* sw1 = wsrc + (long)PW*4;
        for (int i = t; i < 768; i += 512) cpa16(dk1 + i*16, sk1 + i*16);
        if (t < 256) cpa16(dw1 + t*16, sw1 + t*16);
        CP_COMMIT();
    }

    float accA[2][4], accB[2][4];   /* out partials: [ct][frag] per A-tile */
    #pragma unroll
    for (int ct = 0; ct < 2; ++ct)
        #pragma unroll
        for (int i = 0; i < 4; ++i){ accA[ct][i] = 0.f; accB[ct][i] = 0.f; }

    int buf = 0;

    for (int nc = 0; nc < NB; ++nc){
        CP_WAIT1();
        __syncthreads();
        if (nc + 2 < NB){
            const int nb2 = (buf + 2 >= 3) ? buf - 1 : buf + 2;
            const u32 dk = smem_u32(sK + nb2*PA);
            const u32 dw = smem_u32(sW + nb2*PW);
            const char* sk = ksrc + (long)(nc + 2)*PA*4;
            const char* sw = wsrc + (long)(nc + 2)*PW*4;
            for (int i = t; i < 768; i += 512) cpa16(dk + i*16, sk + i*16);
            if (t < 256) cpa16(dw + t*16, sw + t*16);
        }
        CP_COMMIT();

        const u32* curK = sK + buf*PA;
        const u32* curW = sW + buf*PW;

        #pragma unroll
        for (int jj = 0; jj < 2; ++jj){
            const int kk = h*2 + jj;
            const int ctb0 = 2*kk, ctb1 = 2*kk + 1;
            uint2 b00 = *(const uint2*)(curK + (ctb0*3 + 0)*64 + lane*2);
            uint2 b01 = *(const uint2*)(curK + (ctb0*3 + 1)*64 + lane*2);
            uint2 b02 = *(const uint2*)(curK + (ctb0*3 + 2)*64 + lane*2);
            uint2 b10 = *(const uint2*)(curK + (ctb1*3 + 0)*64 + lane*2);
            uint2 b11 = *(const uint2*)(curK + (ctb1*3 + 1)*64 + lane*2);
            uint2 b12 = *(const uint2*)(curK + (ctb1*3 + 2)*64 + lane*2);
            uint2 bw0 = *(const uint2*)(curW + (kk*2 + 0)*64 + lane*2);
            uint2 bw1 = *(const uint2*)(curW + (kk*2 + 1)*64 + lane*2);

            {   /* A-tile 0: S (f16 accum) -> pf -> out += pf x vw */
                u32 s0[2] = {0u, 0u}, s1[2] = {0u, 0u};
                mma_h16(s0, aq0[0], b00); mma_h16(s0, aq0[1], b01); mma_h16(s0, aq0[2], b02);
                mma_h16(s1, aq0[0], b10); mma_h16(s1, aq0[1], b11); mma_h16(s1, aq0[2], b12);
                uint4 pf;
                pf.x = ex2h2(s0[0], hmin);
                pf.y = ex2h2(s0[1], hmin);
                pf.z = ex2h2(s1[0], hmin);
                pf.w = ex2h2(s1[1], hmin);
                mma_h(accA[0], pf, bw0);
                mma_h(accA[1], pf, bw1);
            }
            {   /* A-tile 1 */
                u32 s0[2] = {0u, 0u}, s1[2] = {0u, 0u};
                mma_h16(s0, aq1[0], b00); mma_h16(s0, aq1[1], b01); mma_h16(s0, aq1[2], b02);
                mma_h16(s1, aq1[0], b10); mma_h16(s1, aq1[1], b11); mma_h16(s1, aq1[2], b12);
                uint4 pf;
                pf.x = ex2h2(s0[0], hmin);
                pf.y = ex2h2(s0[1], hmin);
                pf.z = ex2h2(s1[0], hmin);
                pf.w = ex2h2(s1[1], hmin);
                mma_h(accB[0], pf, bw0);
                mma_h(accB[1], pf, bw1);
            }
        }
        buf = (buf + 1 >= 3) ? 0 : buf + 1;
    }

    /* drain copies; 4 serialized accumulate phases into outb[16][132] */
    CP_WAIT0();
    __syncthreads();
    #pragma unroll
    for (int ph = 0; ph < 4; ++ph){
        if (h == ph){
            #pragma unroll
            for (int ct = 0; ct < 2; ++ct){
                const int mA = wg*32 + g, mB = mA + 16, cb = ct*8 + 2*tg;
                if (ph == 0){
                    outb[cb*132 + mA]           = accA[ct][0];
                    outb[(cb + 1)*132 + mA]     = accA[ct][1];
                    outb[cb*132 + mA + 8]       = accA[ct][2];
                    outb[(cb + 1)*132 + mA + 8] = accA[ct][3];
                    outb[cb*132 + mB]           = accB[ct][0];
                    outb[(cb + 1)*132 + mB]     = accB[ct][1];
                    outb[cb*132 + mB + 8]       = accB[ct][2];
                    outb[(cb + 1)*132 + mB + 8] = accB[ct][3];
                } else {
                    outb[cb*132 + mA]           += accA[ct][0];
                    outb[(cb + 1)*132 + mA]     += accA[ct][1];
                    outb[cb*132 + mA + 8]       += accA[ct][2];
                    outb[(cb + 1)*132 + mA + 8] += accA[ct][3];
                    outb[cb*132 + mB]           += accB[ct][0];
                    outb[(cb + 1)*132 + mB]     += accB[ct][1];
                    outb[cb*132 + mB + 8]       += accB[ct][2];
                    outb[(cb + 1)*132 + mB + 8] += accB[ct][3];
                }
            }
        }
        __syncthreads();
    }

    /* write out: 12 x 128 */
    {
        const int og = t >> 7, m = t & 127;
        #pragma unroll
        for (int oo = 0; oo < 3; ++oo){
            const int o = og*3 + oo;
            out[((long)(b*12 + o))*NN + mt*128 + m] = outb[o*132 + m] + bo_s[o];
        }
    }
}

/* ============================== launch =================================== */
extern "C" void kernel_launch(void* const* d_in, const int* in_sizes, int n_in,
                              void* d_out, int out_size)
{
    const float* x  = (const float*)d_in[0];
    const float* wq = (const float*)d_in[1];
    const float* bq = (const float*)d_in[2];
    const float* wk = (const float*)d_in[3];
    const float* bk = (const float*)d_in[4];
    const float* wv = (const float*)d_in[5];
    const float* bv = (const float*)d_in[6];
    const float* wo = (const float*)d_in[7];
    const float* bo = (const float*)d_in[8];
    float* out = (float*)d_out;

    /* qkv dyn smem: 12288*4 + 1296*4 + 108*4 = 54768 (needs opt-in!) */
    cudaFuncSetAttribute(qkv_kernel,
                         cudaFuncAttributeMaxDynamicSharedMemorySize, 54768);
    /* pass2 dyn smem: 3*PA*4 + 3*PW*4 + 64 = 49216 */
    cudaFuncSetAttribute(pass2_kernel,
                         cudaFuncAttributeMaxDynamicSharedMemorySize, 49216);

    qkv_kernel  <<<dim3(NB, 8), 384, 54768>>>(x, wq, bq, wk, bk, wv, bv);
    pass1_kernel<<<dim3(NB, 8), 512>>>(wo);
    pass2_kernel<<<dim3(NB, 8), 512, 49216>>>(bo, out);
}